// round 8
// baseline (speedup 1.0000x reference)
#include <cuda_runtime.h>
#include <cuda_bf16.h>
#include <cstdint>

#define BSZ 4
#define CC  256
#define DD  128
#define NN  4096
#define MM  4095
#define NKT 64              // key tiles of 64

// ---------------- scratch ----------------
__device__ __align__(16) __nv_bfloat16 g_xh[BSZ*NN*CC];
__device__ __align__(16) __nv_bfloat16 g_xl[BSZ*NN*CC];
__device__ __align__(16) __nv_bfloat16 g_Wh[3*CC*DD];
__device__ __align__(16) __nv_bfloat16 g_Wl[3*CC*DD];
__device__ __align__(16) __nv_bfloat16 g_th[BSZ*NN*DD];
__device__ __align__(16) __nv_bfloat16 g_tl[BSZ*NN*DD];
__device__ __align__(16) float g_phi[BSZ*NN*DD];
__device__ __align__(16) float g_gv [BSZ*NN*DD];
__device__ __align__(16) __nv_bfloat16 g_kh[BSZ*NN*DD];
__device__ __align__(16) __nv_bfloat16 g_kl[BSZ*NN*DD];
__device__ __align__(16) __nv_bfloat16 g_vh[BSZ*NN*DD];
__device__ __align__(16) __nv_bfloat16 g_vl[BSZ*NN*DD];
__device__ __align__(16) float g_y[BSZ*NN*DD];

// ---------------- helpers ----------------
__device__ __forceinline__ uint32_t s2u(const void* p){
    uint32_t a;
    asm("{ .reg .u64 t; cvta.to.shared.u64 t, %1; cvt.u32.u64 %0, t; }" : "=r"(a) : "l"(p));
    return a;
}
__device__ __forceinline__ void ldsm_x4(uint32_t* r, uint32_t a){
    asm volatile("ldmatrix.sync.aligned.m8n8.x4.shared.b16 {%0,%1,%2,%3}, [%4];"
        : "=r"(r[0]),"=r"(r[1]),"=r"(r[2]),"=r"(r[3]) : "r"(a));
}
__device__ __forceinline__ void ldsm_x2(uint32_t* r, uint32_t a){
    asm volatile("ldmatrix.sync.aligned.m8n8.x2.shared.b16 {%0,%1}, [%2];"
        : "=r"(r[0]),"=r"(r[1]) : "r"(a));
}
__device__ __forceinline__ void ldsm_x4t(uint32_t* r, uint32_t a){
    asm volatile("ldmatrix.sync.aligned.m8n8.x4.trans.shared.b16 {%0,%1,%2,%3}, [%4];"
        : "=r"(r[0]),"=r"(r[1]),"=r"(r[2]),"=r"(r[3]) : "r"(a));
}
__device__ __forceinline__ void mma16816(float* c, const uint32_t* a, const uint32_t* b){
    asm volatile("mma.sync.aligned.m16n8k16.row.col.f32.bf16.bf16.f32 "
        "{%0,%1,%2,%3}, {%4,%5,%6,%7}, {%8,%9}, {%0,%1,%2,%3};"
        : "+f"(c[0]),"+f"(c[1]),"+f"(c[2]),"+f"(c[3])
        : "r"(a[0]),"r"(a[1]),"r"(a[2]),"r"(a[3]),"r"(b[0]),"r"(b[1]));
}
__device__ __forceinline__ uint32_t packbf(float lo, float hi){
    uint32_t r; asm("cvt.rn.bf16x2.f32 %0, %1, %2;" : "=r"(r) : "f"(hi), "f"(lo)); return r;
}
__device__ __forceinline__ void cpa16(uint32_t s, const void* g){
    asm volatile("cp.async.cg.shared.global [%0], [%1], 16;" :: "r"(s), "l"(g));
}
#define CPA_COMMIT() asm volatile("cp.async.commit_group;" ::: "memory")
__device__ __forceinline__ __nv_bfloat16 bhi(float v){ return __float2bfloat16(v); }
__device__ __forceinline__ __nv_bfloat16 blo(float v, __nv_bfloat16 h){
    return __float2bfloat16(v - __bfloat162float(h));
}

// ---------------- kernel 0: split x and W into bf16 hi/lo ----------------
__global__ void conv_kernel(const float* __restrict__ x,
                            const float* __restrict__ Wt,
                            const float* __restrict__ Wp,
                            const float* __restrict__ Wg)
{
    int i = blockIdx.x * blockDim.x + threadIdx.x;   // float4 index
    if (i < BSZ * NN * CC / 4) {
        float4 v = ((const float4*)x)[i];
        __nv_bfloat16 h0 = bhi(v.x), h1 = bhi(v.y), h2 = bhi(v.z), h3 = bhi(v.w);
        __nv_bfloat162 H01; H01.x = h0; H01.y = h1;
        __nv_bfloat162 H23; H23.x = h2; H23.y = h3;
        __nv_bfloat162 L01; L01.x = blo(v.x, h0); L01.y = blo(v.y, h1);
        __nv_bfloat162 L23; L23.x = blo(v.z, h2); L23.y = blo(v.w, h3);
        *(__nv_bfloat162*)(g_xh + 4 * i)     = H01;
        *(__nv_bfloat162*)(g_xh + 4 * i + 2) = H23;
        *(__nv_bfloat162*)(g_xl + 4 * i)     = L01;
        *(__nv_bfloat162*)(g_xl + 4 * i + 2) = L23;
    }
    if (i < 3 * CC * DD / 4) {
        int wsel = (4 * i) / (CC * DD), r4 = i % (CC * DD / 4);
        const float* Wm = (wsel == 0) ? Wt : (wsel == 1) ? Wp : Wg;
        float4 v = ((const float4*)Wm)[r4];
        __nv_bfloat16 h0 = bhi(v.x), h1 = bhi(v.y), h2 = bhi(v.z), h3 = bhi(v.w);
        __nv_bfloat162 H01; H01.x = h0; H01.y = h1;
        __nv_bfloat162 H23; H23.x = h2; H23.y = h3;
        __nv_bfloat162 L01; L01.x = blo(v.x, h0); L01.y = blo(v.y, h1);
        __nv_bfloat162 L23; L23.x = blo(v.z, h2); L23.y = blo(v.w, h3);
        *(__nv_bfloat162*)(g_Wh + 4 * i)     = H01;
        *(__nv_bfloat162*)(g_Wh + 4 * i + 2) = H23;
        *(__nv_bfloat162*)(g_Wl + 4 * i)     = L01;
        *(__nv_bfloat162*)(g_Wl + 4 * i + 2) = L23;
    }
}

// ---------------- kernel 1: projections via mma.sync bf16x3 ----------------
#define PX_STR 144          // 64 bf16 row + 16B pad
#define PW_STR 272          // 128 bf16 row + 16B pad
#define P_XH 0
#define P_XL 18432
#define P_WH 36864
#define P_WL 54272
#define PROJ_SMEM 71680

__global__ void __launch_bounds__(256, 2) proj_kernel()
{
    extern __shared__ __align__(16) char sm[];
    const uint32_t sb = s2u(sm);
    const int tid = threadIdx.x, w = tid >> 5, lane = tid & 31;
    const int n0 = blockIdx.x * 128, wsel = blockIdx.y;
    const int g = lane >> 2, t = lane & 3;

    const uint4* xh4 = (const uint4*)g_xh;
    const uint4* xl4 = (const uint4*)g_xl;
    const uint4* wh4 = (const uint4*)(g_Wh + wsel * CC * DD);
    const uint4* wl4 = (const uint4*)(g_Wl + wsel * CC * DD);

    float O[16][4];
#pragma unroll
    for (int i = 0; i < 16; i++)
#pragma unroll
        for (int j = 0; j < 4; j++) O[i][j] = 0.f;

    const uint32_t xaddr0 = sb + P_XH + (uint32_t)(w * 16 + (lane & 15)) * PX_STR
                          + (uint32_t)(lane >> 4) * 16;
    const uint32_t waddr0 = sb + P_WH + (uint32_t)(lane & 15) * PW_STR
                          + (uint32_t)(lane >> 4) * 16;

    for (int ch = 0; ch < 4; ch++) {
        __syncthreads();
#pragma unroll
        for (int i = 0; i < 4; i++) {
            int f = tid + i * 256, r = f >> 3, c = f & 7;
            uint32_t off = (uint32_t)r * PX_STR + (uint32_t)c * 16;
            size_t src = (size_t)(n0 + r) * 32 + ch * 8 + c;
            *(uint4*)(sm + P_XH + off) = xh4[src];
            *(uint4*)(sm + P_XL + off) = xl4[src];
        }
#pragma unroll
        for (int i = 0; i < 4; i++) {
            int f = tid + i * 256, r = f >> 4, c = f & 15;
            uint32_t off = (uint32_t)r * PW_STR + (uint32_t)c * 16;
            size_t src = (size_t)(ch * 64 + r) * 16 + c;
            *(uint4*)(sm + P_WH + off) = wh4[src];
            *(uint4*)(sm + P_WL + off) = wl4[src];
        }
        __syncthreads();

#pragma unroll
        for (int kc = 0; kc < 4; kc++) {
            uint32_t Ah[4], Al[4];
            uint32_t xa = xaddr0 + kc * 32;
            ldsm_x4(Ah, xa);
            ldsm_x4(Al, xa + (P_XL - P_XH));
#pragma unroll
            for (int nd = 0; nd < 8; nd++) {
                uint32_t Bh[4], Bl[4];
                uint32_t wa = waddr0 + (uint32_t)kc * 16 * PW_STR + (uint32_t)nd * 32;
                ldsm_x4t(Bh, wa);
                ldsm_x4t(Bl, wa + (P_WL - P_WH));
                mma16816(O[2 * nd],     Ah, &Bh[0]);
                mma16816(O[2 * nd],     Al, &Bh[0]);
                mma16816(O[2 * nd],     Ah, &Bl[0]);
                mma16816(O[2 * nd + 1], Ah, &Bh[2]);
                mma16816(O[2 * nd + 1], Al, &Bh[2]);
                mma16816(O[2 * nd + 1], Ah, &Bl[2]);
            }
        }
    }

    int r0 = n0 + w * 16 + g;
    if (wsel == 0) {
#pragma unroll
        for (int nt = 0; nt < 16; nt++) {
            int c = nt * 8 + t * 2;
            float v0 = O[nt][0], v1 = O[nt][1], v2 = O[nt][2], v3 = O[nt][3];
            __nv_bfloat16 h0 = bhi(v0), h1 = bhi(v1), h2 = bhi(v2), h3 = bhi(v3);
            __nv_bfloat162 H0; H0.x = h0; H0.y = h1;
            __nv_bfloat162 L0; L0.x = blo(v0, h0); L0.y = blo(v1, h1);
            __nv_bfloat162 H1; H1.x = h2; H1.y = h3;
            __nv_bfloat162 L1; L1.x = blo(v2, h2); L1.y = blo(v3, h3);
            *(__nv_bfloat162*)(g_th + (size_t)r0 * DD + c)       = H0;
            *(__nv_bfloat162*)(g_tl + (size_t)r0 * DD + c)       = L0;
            *(__nv_bfloat162*)(g_th + (size_t)(r0 + 8) * DD + c) = H1;
            *(__nv_bfloat162*)(g_tl + (size_t)(r0 + 8) * DD + c) = L1;
        }
    } else {
        float* out = (wsel == 1) ? g_phi : g_gv;
#pragma unroll
        for (int nt = 0; nt < 16; nt++) {
            int c = nt * 8 + t * 2;
            float2 a = {O[nt][0], O[nt][1]};
            float2 b = {O[nt][2], O[nt][3]};
            *(float2*)(out + (size_t)r0 * DD + c)       = a;
            *(float2*)(out + (size_t)(r0 + 8) * DD + c) = b;
        }
    }
}

// ---------------- kernel 2: pool -> K,V hi/lo ----------------
__global__ void pool_kernel()
{
    int i = blockIdx.x * blockDim.x + threadIdx.x;
    if (i >= BSZ * NN * DD) return;
    int m = (i / DD) % NN;
    float kv = 0.f, vv = 0.f;
    if (m < MM) {
        kv = fmaxf(g_phi[i], g_phi[i + DD]);
        vv = fmaxf(g_gv[i],  g_gv[i + DD]);
    }
    __nv_bfloat16 kh = bhi(kv), vh = bhi(vv);
    g_kh[i] = kh; g_kl[i] = blo(kv, kh);
    g_vh[i] = vh; g_vl[i] = blo(vv, vh);
}

// ---------------- kernel 3: flash attention ----------------
// 64 queries/CTA, 128 threads, 2 CTAs/SM, phase-split cp.async K/V pipeline.
#define RSTR   272
#define QH_OFF 0
#define QL_OFF 17408
#define SKH    34816
#define SKL    52224
#define SVH    69632
#define SVL    87040
#define ATT_SMEM 104448

__global__ void __launch_bounds__(128, 2) attn_kernel()
{
    extern __shared__ __align__(16) char sm[];
    const uint32_t sb = s2u(sm);
    const int tid = threadIdx.x, w = tid >> 5, lane = tid & 31;
    const int b = blockIdx.y, q0 = blockIdx.x * 64;
    const int g = lane >> 2, t = lane & 3;

    const uint4* kh4 = (const uint4*)(g_kh + (size_t)b * NN * DD);
    const uint4* kl4 = (const uint4*)(g_kl + (size_t)b * NN * DD);
    const uint4* vh4 = (const uint4*)(g_vh + (size_t)b * NN * DD);
    const uint4* vl4 = (const uint4*)(g_vl + (size_t)b * NN * DD);

    // per-thread load offsets: 8 chunks of 128 threads (1024 uint4 per buffer)
    uint32_t soff[8]; uint32_t goff[8];
#pragma unroll
    for (int i = 0; i < 8; i++) {
        int f = tid + i * 128;
        soff[i] = (uint32_t)(f >> 4) * RSTR + (uint32_t)(f & 15) * 16;
        goff[i] = (uint32_t)f;
    }

    // prologue: issue K0 group, V0 group
#pragma unroll
    for (int i = 0; i < 8; i++) cpa16(sb + SKH + soff[i], kh4 + goff[i]);
#pragma unroll
    for (int i = 0; i < 8; i++) cpa16(sb + SKL + soff[i], kl4 + goff[i]);
    CPA_COMMIT();
#pragma unroll
    for (int i = 0; i < 8; i++) cpa16(sb + SVH + soff[i], vh4 + goff[i]);
#pragma unroll
    for (int i = 0; i < 8; i++) cpa16(sb + SVL + soff[i], vl4 + goff[i]);
    CPA_COMMIT();

    // load Q hi/lo (plain loads, while cp.async flies)
    {
        const uint4* qh = (const uint4*)(g_th + ((size_t)b * NN + q0) * DD);
        const uint4* ql = (const uint4*)(g_tl + ((size_t)b * NN + q0) * DD);
#pragma unroll
        for (int i = 0; i < 8; i++) {
            int f = tid + i * 128;
            uint32_t off = (uint32_t)(f >> 4) * RSTR + (uint32_t)(f & 15) * 16;
            *(uint4*)(sm + QH_OFF + off) = qh[f];
            *(uint4*)(sm + QL_OFF + off) = ql[f];
        }
    }

    float O[16][4];
#pragma unroll
    for (int i = 0; i < 16; i++)
#pragma unroll
        for (int j = 0; j < 4; j++) O[i][j] = 0.f;
    float mA = -1e30f, mB = -1e30f, lA = 0.f, lB = 0.f;

    const uint32_t qaddr0 = sb + QH_OFF + (uint32_t)(w * 16 + (lane & 15)) * RSTR
                          + (uint32_t)(lane >> 4) * 16;
    const uint32_t kaddr0 = sb + SKH + (uint32_t)(lane & 7) * RSTR
                          + (uint32_t)((lane >> 3) & 1) * 16;
    const uint32_t vaddr0 = sb + SVH + (uint32_t)(lane & 15) * RSTR
                          + (uint32_t)(lane >> 4) * 16;

    for (int kt = 0; kt < NKT; kt++) {
        // ---- K_kt ready? (pending: V_kt [, K_kt at top only]) ----
        asm volatile("cp.async.wait_group 1;" ::: "memory");
        __syncthreads();

        // ---- S = Q K^T (bf16x3) ----
        float S[8][4];
#pragma unroll
        for (int i = 0; i < 8; i++)
#pragma unroll
            for (int j = 0; j < 4; j++) S[i][j] = 0.f;

#pragma unroll
        for (int kc = 0; kc < 8; kc++) {
            uint32_t Ah[4], Al[4];
            uint32_t qa = qaddr0 + kc * 32;
            ldsm_x4(Ah, qa);
            ldsm_x4(Al, qa + (QL_OFF - QH_OFF));
#pragma unroll
            for (int nt = 0; nt < 8; nt++) {
                uint32_t Bh[2], Bl[2];
                uint32_t ka = kaddr0 + (uint32_t)nt * 8 * RSTR + kc * 32;
                ldsm_x2(Bh, ka);
                ldsm_x2(Bl, ka + (SKL - SKH));
                mma16816(S[nt], Ah, Bh);
                mma16816(S[nt], Al, Bh);
                mma16816(S[nt], Ah, Bl);
            }
        }
        __syncthreads();      // all warps done reading K buffer

        // prefetch K_{kt+1} into K buffer
        if (kt + 1 < NKT) {
            uint32_t gi = (uint32_t)(kt + 1) * 1024;
#pragma unroll
            for (int i = 0; i < 8; i++) cpa16(sb + SKH + soff[i], kh4 + gi + goff[i]);
#pragma unroll
            for (int i = 0; i < 8; i++) cpa16(sb + SKL + soff[i], kl4 + gi + goff[i]);
            CPA_COMMIT();
        }

        // mask key m=4095 (last col of last tile)
        if (kt == NKT - 1 && t == 3) { S[7][1] = -1e30f; S[7][3] = -1e30f; }

        // ---- online softmax (overlaps V arrival) ----
        float mlA = -1e30f, mlB = -1e30f;
#pragma unroll
        for (int nt = 0; nt < 8; nt++) {
            mlA = fmaxf(mlA, fmaxf(S[nt][0], S[nt][1]));
            mlB = fmaxf(mlB, fmaxf(S[nt][2], S[nt][3]));
        }
        mlA = fmaxf(mlA, __shfl_xor_sync(0xffffffffu, mlA, 1));
        mlA = fmaxf(mlA, __shfl_xor_sync(0xffffffffu, mlA, 2));
        mlB = fmaxf(mlB, __shfl_xor_sync(0xffffffffu, mlB, 1));
        mlB = fmaxf(mlB, __shfl_xor_sync(0xffffffffu, mlB, 2));

        float mnA = fmaxf(mA, mlA), mnB = fmaxf(mB, mlB);
        float scA = __expf(mA - mnA), scB = __expf(mB - mnB);
        mA = mnA; mB = mnB;

        float lsA = 0.f, lsB = 0.f;
#pragma unroll
        for (int nt = 0; nt < 8; nt++) {
            S[nt][0] = __expf(S[nt][0] - mnA);
            S[nt][1] = __expf(S[nt][1] - mnA);
            S[nt][2] = __expf(S[nt][2] - mnB);
            S[nt][3] = __expf(S[nt][3] - mnB);
            lsA += S[nt][0] + S[nt][1];
            lsB += S[nt][2] + S[nt][3];
        }
        lsA += __shfl_xor_sync(0xffffffffu, lsA, 1);
        lsA += __shfl_xor_sync(0xffffffffu, lsA, 2);
        lsB += __shfl_xor_sync(0xffffffffu, lsB, 1);
        lsB += __shfl_xor_sync(0xffffffffu, lsB, 2);
        lA = lA * scA + lsA;
        lB = lB * scB + lsB;

#pragma unroll
        for (int i = 0; i < 16; i++) {
            O[i][0] *= scA; O[i][1] *= scA;
            O[i][2] *= scB; O[i][3] *= scB;
        }

        // ---- V_kt ready? (pending: K_{kt+1} except on last iter) ----
        if (kt + 1 < NKT)
            asm volatile("cp.async.wait_group 1;" ::: "memory");
        else
            asm volatile("cp.async.wait_group 0;" ::: "memory");
        __syncthreads();

        // ---- O += P V (bf16x3) ----
#pragma unroll
        for (int kk = 0; kk < 4; kk++) {
            uint32_t Ph[4], Pl[4];
            {
                const float* s0 = S[2 * kk];
                const float* s1 = S[2 * kk + 1];
                float h[8], lo[8];
#pragma unroll
                for (int e = 0; e < 4; e++) {
                    float p0 = s0[e], p1 = s1[e];
                    float h0 = __uint_as_float(__float_as_uint(p0) & 0xffff0000u);
                    float h1 = __uint_as_float(__float_as_uint(p1) & 0xffff0000u);
                    h[e] = h0; lo[e] = p0 - h0;
                    h[4 + e] = h1; lo[4 + e] = p1 - h1;
                }
                Ph[0] = packbf(h[0], h[1]);  Ph[1] = packbf(h[2], h[3]);
                Ph[2] = packbf(h[4], h[5]);  Ph[3] = packbf(h[6], h[7]);
                Pl[0] = packbf(lo[0], lo[1]); Pl[1] = packbf(lo[2], lo[3]);
                Pl[2] = packbf(lo[4], lo[5]); Pl[3] = packbf(lo[6], lo[7]);
            }
#pragma unroll
            for (int nd = 0; nd < 8; nd++) {
                uint32_t Vh[4], Vl[4];
                uint32_t va = vaddr0 + (uint32_t)kk * 16 * RSTR + (uint32_t)nd * 32;
                ldsm_x4t(Vh, va);
                ldsm_x4t(Vl, va + (SVL - SVH));
                mma16816(O[2 * nd],     Ph, &Vh[0]);
                mma16816(O[2 * nd],     Pl, &Vh[0]);
                mma16816(O[2 * nd],     Ph, &Vl[0]);
                mma16816(O[2 * nd + 1], Ph, &Vh[2]);
                mma16816(O[2 * nd + 1], Pl, &Vh[2]);
                mma16816(O[2 * nd + 1], Ph, &Vl[2]);
            }
        }
        __syncthreads();      // all warps done reading V buffer

        // prefetch V_{kt+1}
        if (kt + 1 < NKT) {
            uint32_t gi = (uint32_t)(kt + 1) * 1024;
#pragma unroll
            for (int i = 0; i < 8; i++) cpa16(sb + SVH + soff[i], vh4 + gi + goff[i]);
#pragma unroll
            for (int i = 0; i < 8; i++) cpa16(sb + SVL + soff[i], vl4 + gi + goff[i]);
            CPA_COMMIT();
        }
    }

    // epilogue
    float invA = 1.f / lA, invB = 1.f / lB;
    float* yA = g_y + ((size_t)b * NN + q0 + w * 16 + g) * DD;
    float* yB = yA + 8 * DD;
#pragma unroll
    for (int nd = 0; nd < 16; nd++) {
        int c = nd * 8 + t * 2;
        float2 oa = {O[nd][0] * invA, O[nd][1] * invA};
        float2 ob = {O[nd][2] * invB, O[nd][3] * invB};
        *(float2*)(yA + c) = oa;
        *(float2*)(yB + c) = ob;
    }
}

// ---------------- kernel 4: z = x + y @ Wf (smem Wf, 8x4 micro) ----------------
#define OY_STR 132
#define OW_STR 68
#define OUT_SMEM (128 * OY_STR * 4 + 128 * OW_STR * 4)   // 102400

__global__ void __launch_bounds__(256, 2) out_kernel(const float* __restrict__ x,
                                                     const float* __restrict__ Wf,
                                                     float* __restrict__ z)
{
    extern __shared__ __align__(16) float osm[];
    float* Ys  = osm;                   // [128][132]
    float* Wfs = osm + 128 * OY_STR;    // [128][68]

    const int tid = threadIdx.x, ty = tid >> 4, tx = tid & 15;
    const int row0 = blockIdx.x * 128, c0 = blockIdx.y * 64;

    {
        const float4* src = (const float4*)(g_y + (size_t)row0 * DD);
#pragma unroll
        for (int p = 0; p < 16; p++) {
            int f = tid + p * 256, r = f >> 5, c = (f & 31) * 4;
            *(float4*)&Ys[r * OY_STR + c] = src[f];
        }
    }
    {
#pragma unroll
        for (int p = 0; p < 8; p++) {
            int f = tid + p * 256, r = f >> 4, c = (f & 15) * 4;
            *(float4*)&Wfs[r * OW_STR + c] = *(const float4*)&Wf[(size_t)r * CC + c0 + c];
        }
    }
    __syncthreads();

    float acc[8][4];
#pragma unroll
    for (int i = 0; i < 8; i++)
#pragma unroll
        for (int j = 0; j < 4; j++) acc[i][j] = 0.f;

#pragma unroll 4
    for (int k = 0; k < DD; k++) {
        float4 wv = *(float4*)&Wfs[k * OW_STR + tx * 4];
        float a[8];
#pragma unroll
        for (int i = 0; i < 8; i++) a[i] = Ys[(ty * 8 + i) * OY_STR + k];
#pragma unroll
        for (int i = 0; i < 8; i++) {
            acc[i][0] = fmaf(a[i], wv.x, acc[i][0]);
            acc[i][1] = fmaf(a[i], wv.y, acc[i][1]);
            acc[i][2] = fmaf(a[i], wv.z, acc[i][2]);
            acc[i][3] = fmaf(a[i], wv.w, acc[i][3]);
        }
    }

#pragma unroll
    for (int i = 0; i < 8; i++) {
        size_t base = (size_t)(row0 + ty * 8 + i) * CC + c0 + tx * 4;
        float4 xv = *(const float4*)&x[base];
        float4 o = {xv.x + acc[i][0], xv.y + acc[i][1], xv.z + acc[i][2], xv.w + acc[i][3]};
        *(float4*)&z[base] = o;
    }
}

// ---------------- launch ----------------
extern "C" void kernel_launch(void* const* d_in, const int* in_sizes, int n_in,
                              void* d_out, int out_size)
{
    const float* x  = (const float*)d_in[0];
    const float* Wt = (const float*)d_in[1];
    const float* Wp = (const float*)d_in[2];
    const float* Wg = (const float*)d_in[3];
    const float* Wf = (const float*)d_in[4];
    float* z = (float*)d_out;

    cudaFuncSetAttribute(proj_kernel, cudaFuncAttributeMaxDynamicSharedMemorySize, PROJ_SMEM);
    cudaFuncSetAttribute(attn_kernel, cudaFuncAttributeMaxDynamicSharedMemorySize, ATT_SMEM);
    cudaFuncSetAttribute(out_kernel,  cudaFuncAttributeMaxDynamicSharedMemorySize, OUT_SMEM);

    conv_kernel<<<(BSZ * NN * CC / 4 + 255) / 256, 256>>>(x, Wt, Wp, Wg);
    proj_kernel<<<dim3(BSZ * NN / 128, 3), 256, PROJ_SMEM>>>();
    pool_kernel<<<(BSZ * NN * DD) / 256, 256>>>();
    attn_kernel<<<dim3(NN / 64, BSZ), 128, ATT_SMEM>>>();
    out_kernel<<<dim3(BSZ * NN / 128, CC / 64), 256, OUT_SMEM>>>(x, Wf, z);
}

// round 10
// speedup vs baseline: 1.1086x; 1.1086x over previous
#include <cuda_runtime.h>
#include <cuda_bf16.h>
#include <cstdint>

#define BSZ 4
#define CC  256
#define DD  128
#define NN  4096
#define MM  4095
#define NKT2 32             // key tiles of 128

// ---------------- scratch ----------------
__device__ __align__(16) __nv_bfloat16 g_xh[BSZ*NN*CC];
__device__ __align__(16) __nv_bfloat16 g_xl[BSZ*NN*CC];
__device__ __align__(16) __nv_bfloat16 g_Wh[3*CC*DD];
__device__ __align__(16) __nv_bfloat16 g_Wl[3*CC*DD];
__device__ __align__(16) __nv_bfloat16 g_th[BSZ*NN*DD];
__device__ __align__(16) __nv_bfloat16 g_tl[BSZ*NN*DD];
__device__ __align__(16) float g_phi[BSZ*NN*DD];
__device__ __align__(16) float g_gv [BSZ*NN*DD];
__device__ __align__(16) __nv_bfloat16 g_kh[BSZ*NN*DD];
__device__ __align__(16) __nv_bfloat16 g_kl[BSZ*NN*DD];
__device__ __align__(16) __nv_bfloat16 g_vh[BSZ*NN*DD];
__device__ __align__(16) __nv_bfloat16 g_vl[BSZ*NN*DD];
__device__ __align__(16) float g_y[BSZ*NN*DD];

// ---------------- helpers ----------------
__device__ __forceinline__ uint32_t s2u(const void* p){
    uint32_t a;
    asm("{ .reg .u64 t; cvta.to.shared.u64 t, %1; cvt.u32.u64 %0, t; }" : "=r"(a) : "l"(p));
    return a;
}
__device__ __forceinline__ void ldsm_x4(uint32_t* r, uint32_t a){
    asm volatile("ldmatrix.sync.aligned.m8n8.x4.shared.b16 {%0,%1,%2,%3}, [%4];"
        : "=r"(r[0]),"=r"(r[1]),"=r"(r[2]),"=r"(r[3]) : "r"(a));
}
__device__ __forceinline__ void ldsm_x2(uint32_t* r, uint32_t a){
    asm volatile("ldmatrix.sync.aligned.m8n8.x2.shared.b16 {%0,%1}, [%2];"
        : "=r"(r[0]),"=r"(r[1]) : "r"(a));
}
__device__ __forceinline__ void ldsm_x4t(uint32_t* r, uint32_t a){
    asm volatile("ldmatrix.sync.aligned.m8n8.x4.trans.shared.b16 {%0,%1,%2,%3}, [%4];"
        : "=r"(r[0]),"=r"(r[1]),"=r"(r[2]),"=r"(r[3]) : "r"(a));
}
__device__ __forceinline__ void mma16816(float* c, const uint32_t* a, const uint32_t* b){
    asm volatile("mma.sync.aligned.m16n8k16.row.col.f32.bf16.bf16.f32 "
        "{%0,%1,%2,%3}, {%4,%5,%6,%7}, {%8,%9}, {%0,%1,%2,%3};"
        : "+f"(c[0]),"+f"(c[1]),"+f"(c[2]),"+f"(c[3])
        : "r"(a[0]),"r"(a[1]),"r"(a[2]),"r"(a[3]),"r"(b[0]),"r"(b[1]));
}
__device__ __forceinline__ uint32_t packbf(float lo, float hi){
    uint32_t r; asm("cvt.rn.bf16x2.f32 %0, %1, %2;" : "=r"(r) : "f"(hi), "f"(lo)); return r;
}
__device__ __forceinline__ void cpa16(uint32_t s, const void* g){
    asm volatile("cp.async.cg.shared.global [%0], [%1], 16;" :: "r"(s), "l"(g));
}
#define CPA_COMMIT() asm volatile("cp.async.commit_group;" ::: "memory")
__device__ __forceinline__ __nv_bfloat16 bhi(float v){ return __float2bfloat16(v); }
__device__ __forceinline__ __nv_bfloat16 blo(float v, __nv_bfloat16 h){
    return __float2bfloat16(v - __bfloat162float(h));
}

// ---------------- kernel 0: split x and W into bf16 hi/lo ----------------
__global__ void conv_kernel(const float* __restrict__ x,
                            const float* __restrict__ Wt,
                            const float* __restrict__ Wp,
                            const float* __restrict__ Wg)
{
    int i = blockIdx.x * blockDim.x + threadIdx.x;
    if (i < BSZ * NN * CC / 4) {
        float4 v = ((const float4*)x)[i];
        __nv_bfloat16 h0 = bhi(v.x), h1 = bhi(v.y), h2 = bhi(v.z), h3 = bhi(v.w);
        __nv_bfloat162 H01; H01.x = h0; H01.y = h1;
        __nv_bfloat162 H23; H23.x = h2; H23.y = h3;
        __nv_bfloat162 L01; L01.x = blo(v.x, h0); L01.y = blo(v.y, h1);
        __nv_bfloat162 L23; L23.x = blo(v.z, h2); L23.y = blo(v.w, h3);
        *(__nv_bfloat162*)(g_xh + 4 * i)     = H01;
        *(__nv_bfloat162*)(g_xh + 4 * i + 2) = H23;
        *(__nv_bfloat162*)(g_xl + 4 * i)     = L01;
        *(__nv_bfloat162*)(g_xl + 4 * i + 2) = L23;
    }
    if (i < 3 * CC * DD / 4) {
        int wsel = (4 * i) / (CC * DD), r4 = i % (CC * DD / 4);
        const float* Wm = (wsel == 0) ? Wt : (wsel == 1) ? Wp : Wg;
        float4 v = ((const float4*)Wm)[r4];
        __nv_bfloat16 h0 = bhi(v.x), h1 = bhi(v.y), h2 = bhi(v.z), h3 = bhi(v.w);
        __nv_bfloat162 H01; H01.x = h0; H01.y = h1;
        __nv_bfloat162 H23; H23.x = h2; H23.y = h3;
        __nv_bfloat162 L01; L01.x = blo(v.x, h0); L01.y = blo(v.y, h1);
        __nv_bfloat162 L23; L23.x = blo(v.z, h2); L23.y = blo(v.w, h3);
        *(__nv_bfloat162*)(g_Wh + 4 * i)     = H01;
        *(__nv_bfloat162*)(g_Wh + 4 * i + 2) = H23;
        *(__nv_bfloat162*)(g_Wl + 4 * i)     = L01;
        *(__nv_bfloat162*)(g_Wl + 4 * i + 2) = L23;
    }
}

// ---------------- kernel 1: projections via mma.sync bf16x3 ----------------
#define PX_STR 144
#define PW_STR 272
#define P_XH 0
#define P_XL 18432
#define P_WH 36864
#define P_WL 54272
#define PROJ_SMEM 71680
#define LOG2E 1.4426950408889634f

__global__ void __launch_bounds__(256, 2) proj_kernel()
{
    extern __shared__ __align__(16) char sm[];
    const uint32_t sb = s2u(sm);
    const int tid = threadIdx.x, w = tid >> 5, lane = tid & 31;
    const int n0 = blockIdx.x * 128, wsel = blockIdx.y;
    const int g = lane >> 2, t = lane & 3;

    const uint4* xh4 = (const uint4*)g_xh;
    const uint4* xl4 = (const uint4*)g_xl;
    const uint4* wh4 = (const uint4*)(g_Wh + wsel * CC * DD);
    const uint4* wl4 = (const uint4*)(g_Wl + wsel * CC * DD);

    float O[16][4];
#pragma unroll
    for (int i = 0; i < 16; i++)
#pragma unroll
        for (int j = 0; j < 4; j++) O[i][j] = 0.f;

    const uint32_t xaddr0 = sb + P_XH + (uint32_t)(w * 16 + (lane & 15)) * PX_STR
                          + (uint32_t)(lane >> 4) * 16;
    const uint32_t waddr0 = sb + P_WH + (uint32_t)(lane & 15) * PW_STR
                          + (uint32_t)(lane >> 4) * 16;

    for (int ch = 0; ch < 4; ch++) {
        __syncthreads();
#pragma unroll
        for (int i = 0; i < 4; i++) {
            int f = tid + i * 256, r = f >> 3, c = f & 7;
            uint32_t off = (uint32_t)r * PX_STR + (uint32_t)c * 16;
            size_t src = (size_t)(n0 + r) * 32 + ch * 8 + c;
            *(uint4*)(sm + P_XH + off) = xh4[src];
            *(uint4*)(sm + P_XL + off) = xl4[src];
        }
#pragma unroll
        for (int i = 0; i < 4; i++) {
            int f = tid + i * 256, r = f >> 4, c = f & 15;
            uint32_t off = (uint32_t)r * PW_STR + (uint32_t)c * 16;
            size_t src = (size_t)(ch * 64 + r) * 16 + c;
            *(uint4*)(sm + P_WH + off) = wh4[src];
            *(uint4*)(sm + P_WL + off) = wl4[src];
        }
        __syncthreads();

#pragma unroll
        for (int kc = 0; kc < 4; kc++) {
            uint32_t Ah[4], Al[4];
            uint32_t xa = xaddr0 + kc * 32;
            ldsm_x4(Ah, xa);
            ldsm_x4(Al, xa + (P_XL - P_XH));
#pragma unroll
            for (int nd = 0; nd < 8; nd++) {
                uint32_t Bh[4], Bl[4];
                uint32_t wa = waddr0 + (uint32_t)kc * 16 * PW_STR + (uint32_t)nd * 32;
                ldsm_x4t(Bh, wa);
                ldsm_x4t(Bl, wa + (P_WL - P_WH));
                mma16816(O[2 * nd],     Ah, &Bh[0]);
                mma16816(O[2 * nd],     Al, &Bh[0]);
                mma16816(O[2 * nd],     Ah, &Bl[0]);
                mma16816(O[2 * nd + 1], Ah, &Bh[2]);
                mma16816(O[2 * nd + 1], Al, &Bh[2]);
                mma16816(O[2 * nd + 1], Ah, &Bl[2]);
            }
        }
    }

    int r0 = n0 + w * 16 + g;
    if (wsel == 0) {
        // theta: pre-scale by log2(e) so attention can use exp2
#pragma unroll
        for (int nt = 0; nt < 16; nt++) {
            int c = nt * 8 + t * 2;
            float v0 = O[nt][0] * LOG2E, v1 = O[nt][1] * LOG2E;
            float v2 = O[nt][2] * LOG2E, v3 = O[nt][3] * LOG2E;
            __nv_bfloat16 h0 = bhi(v0), h1 = bhi(v1), h2 = bhi(v2), h3 = bhi(v3);
            __nv_bfloat162 H0; H0.x = h0; H0.y = h1;
            __nv_bfloat162 L0; L0.x = blo(v0, h0); L0.y = blo(v1, h1);
            __nv_bfloat162 H1; H1.x = h2; H1.y = h3;
            __nv_bfloat162 L1; L1.x = blo(v2, h2); L1.y = blo(v3, h3);
            *(__nv_bfloat162*)(g_th + (size_t)r0 * DD + c)       = H0;
            *(__nv_bfloat162*)(g_tl + (size_t)r0 * DD + c)       = L0;
            *(__nv_bfloat162*)(g_th + (size_t)(r0 + 8) * DD + c) = H1;
            *(__nv_bfloat162*)(g_tl + (size_t)(r0 + 8) * DD + c) = L1;
        }
    } else {
        float* out = (wsel == 1) ? g_phi : g_gv;
#pragma unroll
        for (int nt = 0; nt < 16; nt++) {
            int c = nt * 8 + t * 2;
            float2 a = {O[nt][0], O[nt][1]};
            float2 b = {O[nt][2], O[nt][3]};
            *(float2*)(out + (size_t)r0 * DD + c)       = a;
            *(float2*)(out + (size_t)(r0 + 8) * DD + c) = b;
        }
    }
}

// ---------------- kernel 2: pool -> K,V hi/lo ----------------
__global__ void pool_kernel()
{
    int i = blockIdx.x * blockDim.x + threadIdx.x;
    if (i >= BSZ * NN * DD) return;
    int m = (i / DD) % NN;
    float kv = 0.f, vv = 0.f;
    if (m < MM) {
        kv = fmaxf(g_phi[i], g_phi[i + DD]);
        vv = fmaxf(g_gv[i],  g_gv[i + DD]);
    }
    __nv_bfloat16 kh = bhi(kv), vh = bhi(vv);
    g_kh[i] = kh; g_kl[i] = blo(kv, kh);
    g_vh[i] = vh; g_vl[i] = blo(vv, vh);
}

// ---------------- kernel 3: flash attention ----------------
// 128 queries/CTA, 256 threads, 128-key tiles, phase-split single-buffer cp.async.
#define RSTR   272
#define QH_OFF 0
#define QL_OFF 34816
#define SKH    69632
#define SKL    104448
#define SVH    139264
#define SVL    174080
#define ATT_SMEM 208896

__global__ void __launch_bounds__(256, 1) attn_kernel()
{
    extern __shared__ __align__(16) char sm[];
    const uint32_t sb = s2u(sm);
    const int tid = threadIdx.x, w = tid >> 5, lane = tid & 31;
    const int b = blockIdx.y, q0 = blockIdx.x * 128;
    const int g = lane >> 2, t = lane & 3;

    const uint4* kh4 = (const uint4*)(g_kh + (size_t)b * NN * DD);
    const uint4* kl4 = (const uint4*)(g_kl + (size_t)b * NN * DD);
    const uint4* vh4 = (const uint4*)(g_vh + (size_t)b * NN * DD);
    const uint4* vl4 = (const uint4*)(g_vl + (size_t)b * NN * DD);

    // per-thread load offsets: 2048 uint4 per half-buffer, 8 chunks of 256 threads
    uint32_t soff[8]; uint32_t goff[8];
#pragma unroll
    for (int i = 0; i < 8; i++) {
        int f = tid + i * 256;
        soff[i] = (uint32_t)(f >> 4) * RSTR + (uint32_t)(f & 15) * 16;
        goff[i] = (uint32_t)f;
    }

    // prologue: K0 group, V0 group
#pragma unroll
    for (int i = 0; i < 8; i++) cpa16(sb + SKH + soff[i], kh4 + goff[i]);
#pragma unroll
    for (int i = 0; i < 8; i++) cpa16(sb + SKL + soff[i], kl4 + goff[i]);
    CPA_COMMIT();
#pragma unroll
    for (int i = 0; i < 8; i++) cpa16(sb + SVH + soff[i], vh4 + goff[i]);
#pragma unroll
    for (int i = 0; i < 8; i++) cpa16(sb + SVL + soff[i], vl4 + goff[i]);
    CPA_COMMIT();

    // load Q hi/lo (plain loads, overlap with cp.async)
    {
        const uint4* qh = (const uint4*)(g_th + ((size_t)b * NN + q0) * DD);
        const uint4* ql = (const uint4*)(g_tl + ((size_t)b * NN + q0) * DD);
#pragma unroll
        for (int i = 0; i < 8; i++) {
            int f = tid + i * 256;
            uint32_t off = (uint32_t)(f >> 4) * RSTR + (uint32_t)(f & 15) * 16;
            *(uint4*)(sm + QH_OFF + off) = qh[f];
            *(uint4*)(sm + QL_OFF + off) = ql[f];
        }
    }

    float O[16][4];
#pragma unroll
    for (int i = 0; i < 16; i++)
#pragma unroll
        for (int j = 0; j < 4; j++) O[i][j] = 0.f;
    float mA = -1e30f, mB = -1e30f, lA = 0.f, lB = 0.f;

    const uint32_t qaddr0 = sb + QH_OFF + (uint32_t)(w * 16 + (lane & 15)) * RSTR
                          + (uint32_t)(lane >> 4) * 16;
    const uint32_t kaddr0 = sb + SKH + (uint32_t)(lane & 7) * RSTR
                          + (uint32_t)((lane >> 3) & 1) * 16;
    const uint32_t vaddr0 = sb + SVH + (uint32_t)(lane & 15) * RSTR
                          + (uint32_t)(lane >> 4) * 16;

    for (int kt = 0; kt < NKT2; kt++) {
        // K_kt ready (pending: V_kt)
        asm volatile("cp.async.wait_group 1;" ::: "memory");
        __syncthreads();

        // ---- S = Q K^T (bf16x3), 128 keys ----
        float S[16][4];
#pragma unroll
        for (int i = 0; i < 16; i++)
#pragma unroll
            for (int j = 0; j < 4; j++) S[i][j] = 0.f;

#pragma unroll
        for (int kc = 0; kc < 8; kc++) {
            uint32_t Ah[4], Al[4];
            uint32_t qa = qaddr0 + kc * 32;
            ldsm_x4(Ah, qa);
            ldsm_x4(Al, qa + (QL_OFF - QH_OFF));
#pragma unroll
            for (int nt = 0; nt < 16; nt++) {
                uint32_t Bh[2], Bl[2];
                uint32_t ka = kaddr0 + (uint32_t)nt * 8 * RSTR + kc * 32;
                ldsm_x2(Bh, ka);
                ldsm_x2(Bl, ka + (SKL - SKH));
                mma16816(S[nt], Ah, Bh);
                mma16816(S[nt], Al, Bh);
                mma16816(S[nt], Ah, Bl);
            }
        }
        __syncthreads();      // all warps done reading K buffer

        // prefetch K_{kt+1}
        if (kt + 1 < NKT2) {
            uint32_t gi = (uint32_t)(kt + 1) * 2048;
#pragma unroll
            for (int i = 0; i < 8; i++) cpa16(sb + SKH + soff[i], kh4 + gi + goff[i]);
#pragma unroll
            for (int i = 0; i < 8; i++) cpa16(sb + SKL + soff[i], kl4 + gi + goff[i]);
            CPA_COMMIT();
        }

        // mask key m=4095 (nt=15, col 127 -> t==3 elems 1,3)
        if (kt == NKT2 - 1 && t == 3) { S[15][1] = -1e30f; S[15][3] = -1e30f; }

        // ---- online softmax (base-2 domain; theta pre-scaled by log2 e) ----
        float mlA = -1e30f, mlB = -1e30f;
#pragma unroll
        for (int nt = 0; nt < 16; nt++) {
            mlA = fmaxf(mlA, fmaxf(S[nt][0], S[nt][1]));
            mlB = fmaxf(mlB, fmaxf(S[nt][2], S[nt][3]));
        }
        mlA = fmaxf(mlA, __shfl_xor_sync(0xffffffffu, mlA, 1));
        mlA = fmaxf(mlA, __shfl_xor_sync(0xffffffffu, mlA, 2));
        mlB = fmaxf(mlB, __shfl_xor_sync(0xffffffffu, mlB, 1));
        mlB = fmaxf(mlB, __shfl_xor_sync(0xffffffffu, mlB, 2));

        float mnA = fmaxf(mA, mlA), mnB = fmaxf(mB, mlB);
        float scA = exp2f(mA - mnA), scB = exp2f(mB - mnB);
        mA = mnA; mB = mnB;

        float lsA = 0.f, lsB = 0.f;
#pragma unroll
        for (int nt = 0; nt < 16; nt++) {
            S[nt][0] = exp2f(S[nt][0] - mnA);
            S[nt][1] = exp2f(S[nt][1] - mnA);
            S[nt][2] = exp2f(S[nt][2] - mnB);
            S[nt][3] = exp2f(S[nt][3] - mnB);
            lsA += S[nt][0] + S[nt][1];
            lsB += S[nt][2] + S[nt][3];
        }
        lsA += __shfl_xor_sync(0xffffffffu, lsA, 1);
        lsA += __shfl_xor_sync(0xffffffffu, lsA, 2);
        lsB += __shfl_xor_sync(0xffffffffu, lsB, 1);
        lsB += __shfl_xor_sync(0xffffffffu, lsB, 2);
        lA = lA * scA + lsA;
        lB = lB * scB + lsB;

#pragma unroll
        for (int i = 0; i < 16; i++) {
            O[i][0] *= scA; O[i][1] *= scA;
            O[i][2] *= scB; O[i][3] *= scB;
        }

        // V_kt ready (pending: K_{kt+1} unless last)
        if (kt + 1 < NKT2)
            asm volatile("cp.async.wait_group 1;" ::: "memory");
        else
            asm volatile("cp.async.wait_group 0;" ::: "memory");
        __syncthreads();

        // ---- O += P V (bf16x3), 128 keys: kk 0..7 ----
#pragma unroll
        for (int kk = 0; kk < 8; kk++) {
            uint32_t Ph[4], Pl[4];
            {
                const float* s0 = S[2 * kk];
                const float* s1 = S[2 * kk + 1];
                float lo[8];
#pragma unroll
                for (int e = 0; e < 4; e++) {
                    float p0 = s0[e], p1 = s1[e];
                    float h0 = __uint_as_float(__float_as_uint(p0) & 0xffff0000u);
                    float h1 = __uint_as_float(__float_as_uint(p1) & 0xffff0000u);
                    lo[e] = p0 - h0; lo[4 + e] = p1 - h1;
                }
                Ph[0] = __byte_perm(__float_as_uint(s0[0]), __float_as_uint(s0[1]), 0x7632);
                Ph[1] = __byte_perm(__float_as_uint(s0[2]), __float_as_uint(s0[3]), 0x7632);
                Ph[2] = __byte_perm(__float_as_uint(s1[0]), __float_as_uint(s1[1]), 0x7632);
                Ph[3] = __byte_perm(__float_as_uint(s1[2]), __float_as_uint(s1[3]), 0x7632);
                Pl[0] = packbf(lo[0], lo[1]); Pl[1] = packbf(lo[2], lo[3]);
                Pl[2] = packbf(lo[4], lo[5]); Pl[3] = packbf(lo[6], lo[7]);
            }
#pragma unroll
            for (int nd = 0; nd < 8; nd++) {
                uint32_t Vh[4], Vl[4];
                uint32_t va = vaddr0 + (uint32_t)kk * 16 * RSTR + (uint32_t)nd * 32;
                ldsm_x4t(Vh, va);
                ldsm_x4t(Vl, va + (SVL - SVH));
                mma16816(O[2 * nd],     Ph, &Vh[0]);
                mma16816(O[2 * nd],     Pl, &Vh[0]);
                mma16816(O[2 * nd],     Ph, &Vl[0]);
                mma16816(O[2 * nd + 1], Ph, &Vh[2]);
                mma16816(O[2 * nd + 1], Pl, &Vh[2]);
                mma16816(O[2 * nd + 1], Ph, &Vl[2]);
            }
        }
        __syncthreads();      // all warps done reading V buffer

        // prefetch V_{kt+1}
        if (kt + 1 < NKT2) {
            uint32_t gi = (uint32_t)(kt + 1) * 2048;
#pragma unroll
            for (int i = 0; i < 8; i++) cpa16(sb + SVH + soff[i], vh4 + gi + goff[i]);
#pragma unroll
            for (int i = 0; i < 8; i++) cpa16(sb + SVL + soff[i], vl4 + gi + goff[i]);
            CPA_COMMIT();
        }
    }

    // epilogue
    float invA = 1.f / lA, invB = 1.f / lB;
    float* yA = g_y + ((size_t)b * NN + q0 + w * 16 + g) * DD;
    float* yB = yA + 8 * DD;
#pragma unroll
    for (int nd = 0; nd < 16; nd++) {
        int c = nd * 8 + t * 2;
        float2 oa = {O[nd][0] * invA, O[nd][1] * invA};
        float2 ob = {O[nd][2] * invB, O[nd][3] * invB};
        *(float2*)(yA + c) = oa;
        *(float2*)(yB + c) = ob;
    }
}

// ---------------- kernel 4: z = x + y @ Wf ----------------
#define OY_STR 132
#define OW_STR 68
#define OUT_SMEM (128 * OY_STR * 4 + 128 * OW_STR * 4)

__global__ void __launch_bounds__(256, 2) out_kernel(const float* __restrict__ x,
                                                     const float* __restrict__ Wf,
                                                     float* __restrict__ z)
{
    extern __shared__ __align__(16) float osm[];
    float* Ys  = osm;
    float* Wfs = osm + 128 * OY_STR;

    const int tid = threadIdx.x, ty = tid >> 4, tx = tid & 15;
    const int row0 = blockIdx.x * 128, c0 = blockIdx.y * 64;

    {
        const float4* src = (const float4*)(g_y + (size_t)row0 * DD);
#pragma unroll
        for (int p = 0; p < 16; p++) {
            int f = tid + p * 256, r = f >> 5, c = (f & 31) * 4;
            *(float4*)&Ys[r * OY_STR + c] = src[f];
        }
    }
    {
#pragma unroll
        for (int p = 0; p < 8; p++) {
            int f = tid + p * 256, r = f >> 4, c = (f & 15) * 4;
            *(float4*)&Wfs[r * OW_STR + c] = *(const float4*)&Wf[(size_t)r * CC + c0 + c];
        }
    }
    __syncthreads();

    float acc[8][4];
#pragma unroll
    for (int i = 0; i < 8; i++)
#pragma unroll
        for (int j = 0; j < 4; j++) acc[i][j] = 0.f;

#pragma unroll 4
    for (int k = 0; k < DD; k++) {
        float4 wv = *(float4*)&Wfs[k * OW_STR + tx * 4];
        float a[8];
#pragma unroll
        for (int i = 0; i < 8; i++) a[i] = Ys[(ty * 8 + i) * OY_STR + k];
#pragma unroll
        for (int i = 0; i < 8; i++) {
            acc[i][0] = fmaf(a[i], wv.x, acc[i][0]);
            acc[i][1] = fmaf(a[i], wv.y, acc[i][1]);
            acc[i][2] = fmaf(a[i], wv.z, acc[i][2]);
            acc[i][3] = fmaf(a[i], wv.w, acc[i][3]);
        }
    }

#pragma unroll
    for (int i = 0; i < 8; i++) {
        size_t base = (size_t)(row0 + ty * 8 + i) * CC + c0 + tx * 4;
        float4 xv = *(const float4*)&x[base];
        float4 o = {xv.x + acc[i][0], xv.y + acc[i][1], xv.z + acc[i][2], xv.w + acc[i][3]};
        *(float4*)&z[base] = o;
    }
}

// ---------------- launch ----------------
extern "C" void kernel_launch(void* const* d_in, const int* in_sizes, int n_in,
                              void* d_out, int out_size)
{
    const float* x  = (const float*)d_in[0];
    const float* Wt = (const float*)d_in[1];
    const float* Wp = (const float*)d_in[2];
    const float* Wg = (const float*)d_in[3];
    const float* Wf = (const float*)d_in[4];
    float* z = (float*)d_out;

    cudaFuncSetAttribute(proj_kernel, cudaFuncAttributeMaxDynamicSharedMemorySize, PROJ_SMEM);
    cudaFuncSetAttribute(attn_kernel, cudaFuncAttributeMaxDynamicSharedMemorySize, ATT_SMEM);
    cudaFuncSetAttribute(out_kernel,  cudaFuncAttributeMaxDynamicSharedMemorySize, OUT_SMEM);

    conv_kernel<<<(BSZ * NN * CC / 4 + 255) / 256, 256>>>(x, Wt, Wp, Wg);
    proj_kernel<<<dim3(BSZ * NN / 128, 3), 256, PROJ_SMEM>>>();
    pool_kernel<<<(BSZ * NN * DD) / 256, 256>>>();
    attn_kernel<<<dim3(NN / 128, BSZ), 256, ATT_SMEM>>>();
    out_kernel<<<dim3(BSZ * NN / 128, CC / 64), 256, OUT_SMEM>>>(x, Wf, z);
}

// round 12
// speedup vs baseline: 1.1142x; 1.0051x over previous
#include <cuda_runtime.h>
#include <cuda_bf16.h>
#include <cstdint>

#define BSZ 4
#define CC  256
#define DD  128
#define NN  4096
#define MM  4095
#define NKT 64              // key tiles of 64

// ---------------- scratch ----------------
__device__ __align__(16) __nv_bfloat16 g_xh[BSZ*NN*CC];
__device__ __align__(16) __nv_bfloat16 g_xl[BSZ*NN*CC];
__device__ __align__(16) __nv_bfloat16 g_Wh[3*CC*DD];
__device__ __align__(16) __nv_bfloat16 g_Wl[3*CC*DD];
__device__ __align__(16) __nv_bfloat16 g_th[BSZ*NN*DD];
__device__ __align__(16) __nv_bfloat16 g_tl[BSZ*NN*DD];
__device__ __align__(16) float g_phi[BSZ*NN*DD];
__device__ __align__(16) float g_gv [BSZ*NN*DD];
__device__ __align__(16) __nv_bfloat16 g_kh[BSZ*NN*DD];
__device__ __align__(16) __nv_bfloat16 g_kl[BSZ*NN*DD];
__device__ __align__(16) __nv_bfloat16 g_vh[BSZ*NN*DD];
__device__ __align__(16) __nv_bfloat16 g_vl[BSZ*NN*DD];
__device__ __align__(16) float g_y[BSZ*NN*DD];

// ---------------- helpers ----------------
__device__ __forceinline__ uint32_t s2u(const void* p){
    uint32_t a;
    asm("{ .reg .u64 t; cvta.to.shared.u64 t, %1; cvt.u32.u64 %0, t; }" : "=r"(a) : "l"(p));
    return a;
}
__device__ __forceinline__ void ldsm_x4(uint32_t* r, uint32_t a){
    asm volatile("ldmatrix.sync.aligned.m8n8.x4.shared.b16 {%0,%1,%2,%3}, [%4];"
        : "=r"(r[0]),"=r"(r[1]),"=r"(r[2]),"=r"(r[3]) : "r"(a));
}
__device__ __forceinline__ void ldsm_x4t(uint32_t* r, uint32_t a){
    asm volatile("ldmatrix.sync.aligned.m8n8.x4.trans.shared.b16 {%0,%1,%2,%3}, [%4];"
        : "=r"(r[0]),"=r"(r[1]),"=r"(r[2]),"=r"(r[3]) : "r"(a));
}
__device__ __forceinline__ void mma16816(float* c, const uint32_t* a, const uint32_t* b){
    asm volatile("mma.sync.aligned.m16n8k16.row.col.f32.bf16.bf16.f32 "
        "{%0,%1,%2,%3}, {%4,%5,%6,%7}, {%8,%9}, {%0,%1,%2,%3};"
        : "+f"(c[0]),"+f"(c[1]),"+f"(c[2]),"+f"(c[3])
        : "r"(a[0]),"r"(a[1]),"r"(a[2]),"r"(a[3]),"r"(b[0]),"r"(b[1]));
}
__device__ __forceinline__ uint32_t packbf(float lo, float hi){
    uint32_t r; asm("cvt.rn.bf16x2.f32 %0, %1, %2;" : "=r"(r) : "f"(hi), "f"(lo)); return r;
}
__device__ __forceinline__ void cpa16(uint32_t s, const void* g){
    asm volatile("cp.async.cg.shared.global [%0], [%1], 16;" :: "r"(s), "l"(g));
}
#define CPA_COMMIT() asm volatile("cp.async.commit_group;" ::: "memory")
__device__ __forceinline__ __nv_bfloat16 bhi(float v){ return __float2bfloat16(v); }
__device__ __forceinline__ __nv_bfloat16 blo(float v, __nv_bfloat16 h){
    return __float2bfloat16(v - __bfloat162float(h));
}

// ---------------- kernel 0: split x and W into bf16 hi/lo ----------------
__global__ void conv_kernel(const float* __restrict__ x,
                            const float* __restrict__ Wt,
                            const float* __restrict__ Wp,
                            const float* __restrict__ Wg)
{
    int i = blockIdx.x * blockDim.x + threadIdx.x;
    if (i < BSZ * NN * CC / 4) {
        float4 v = ((const float4*)x)[i];
        __nv_bfloat16 h0 = bhi(v.x), h1 = bhi(v.y), h2 = bhi(v.z), h3 = bhi(v.w);
        __nv_bfloat162 H01; H01.x = h0; H01.y = h1;
        __nv_bfloat162 H23; H23.x = h2; H23.y = h3;
        __nv_bfloat162 L01; L01.x = blo(v.x, h0); L01.y = blo(v.y, h1);
        __nv_bfloat162 L23; L23.x = blo(v.z, h2); L23.y = blo(v.w, h3);
        *(__nv_bfloat162*)(g_xh + 4 * i)     = H01;
        *(__nv_bfloat162*)(g_xh + 4 * i + 2) = H23;
        *(__nv_bfloat162*)(g_xl + 4 * i)     = L01;
        *(__nv_bfloat162*)(g_xl + 4 * i + 2) = L23;
    }
    if (i < 3 * CC * DD / 4) {
        int wsel = (4 * i) / (CC * DD), r4 = i % (CC * DD / 4);
        const float* Wm = (wsel == 0) ? Wt : (wsel == 1) ? Wp : Wg;
        float4 v = ((const float4*)Wm)[r4];
        __nv_bfloat16 h0 = bhi(v.x), h1 = bhi(v.y), h2 = bhi(v.z), h3 = bhi(v.w);
        __nv_bfloat162 H01; H01.x = h0; H01.y = h1;
        __nv_bfloat162 H23; H23.x = h2; H23.y = h3;
        __nv_bfloat162 L01; L01.x = blo(v.x, h0); L01.y = blo(v.y, h1);
        __nv_bfloat162 L23; L23.x = blo(v.z, h2); L23.y = blo(v.w, h3);
        *(__nv_bfloat162*)(g_Wh + 4 * i)     = H01;
        *(__nv_bfloat162*)(g_Wh + 4 * i + 2) = H23;
        *(__nv_bfloat162*)(g_Wl + 4 * i)     = L01;
        *(__nv_bfloat162*)(g_Wl + 4 * i + 2) = L23;
    }
}

// ---------------- kernel 1: projections via mma.sync bf16x3 ----------------
#define PX_STR 144
#define PW_STR 272
#define P_XH 0
#define P_XL 18432
#define P_WH 36864
#define P_WL 54272
#define PROJ_SMEM 71680
#define LOG2E 1.4426950408889634f

__global__ void __launch_bounds__(256, 2) proj_kernel()
{
    extern __shared__ __align__(16) char sm[];
    const uint32_t sb = s2u(sm);
    const int tid = threadIdx.x, w = tid >> 5, lane = tid & 31;
    const int n0 = blockIdx.x * 128, wsel = blockIdx.y;
    const int g = lane >> 2, t = lane & 3;

    const uint4* xh4 = (const uint4*)g_xh;
    const uint4* xl4 = (const uint4*)g_xl;
    const uint4* wh4 = (const uint4*)(g_Wh + wsel * CC * DD);
    const uint4* wl4 = (const uint4*)(g_Wl + wsel * CC * DD);

    float O[16][4];
#pragma unroll
    for (int i = 0; i < 16; i++)
#pragma unroll
        for (int j = 0; j < 4; j++) O[i][j] = 0.f;

    const uint32_t xaddr0 = sb + P_XH + (uint32_t)(w * 16 + (lane & 15)) * PX_STR
                          + (uint32_t)(lane >> 4) * 16;
    const uint32_t waddr0 = sb + P_WH + (uint32_t)(lane & 15) * PW_STR
                          + (uint32_t)(lane >> 4) * 16;

    for (int ch = 0; ch < 4; ch++) {
        __syncthreads();
#pragma unroll
        for (int i = 0; i < 4; i++) {
            int f = tid + i * 256, r = f >> 3, c = f & 7;
            uint32_t off = (uint32_t)r * PX_STR + (uint32_t)c * 16;
            size_t src = (size_t)(n0 + r) * 32 + ch * 8 + c;
            *(uint4*)(sm + P_XH + off) = xh4[src];
            *(uint4*)(sm + P_XL + off) = xl4[src];
        }
#pragma unroll
        for (int i = 0; i < 4; i++) {
            int f = tid + i * 256, r = f >> 4, c = f & 15;
            uint32_t off = (uint32_t)r * PW_STR + (uint32_t)c * 16;
            size_t src = (size_t)(ch * 64 + r) * 16 + c;
            *(uint4*)(sm + P_WH + off) = wh4[src];
            *(uint4*)(sm + P_WL + off) = wl4[src];
        }
        __syncthreads();

#pragma unroll
        for (int kc = 0; kc < 4; kc++) {
            uint32_t Ah[4], Al[4];
            uint32_t xa = xaddr0 + kc * 32;
            ldsm_x4(Ah, xa);
            ldsm_x4(Al, xa + (P_XL - P_XH));
#pragma unroll
            for (int nd = 0; nd < 8; nd++) {
                uint32_t Bh[4], Bl[4];
                uint32_t wa = waddr0 + (uint32_t)kc * 16 * PW_STR + (uint32_t)nd * 32;
                ldsm_x4t(Bh, wa);
                ldsm_x4t(Bl, wa + (P_WL - P_WH));
                mma16816(O[2 * nd],     Ah, &Bh[0]);
                mma16816(O[2 * nd],     Al, &Bh[0]);
                mma16816(O[2 * nd],     Ah, &Bl[0]);
                mma16816(O[2 * nd + 1], Ah, &Bh[2]);
                mma16816(O[2 * nd + 1], Al, &Bh[2]);
                mma16816(O[2 * nd + 1], Ah, &Bl[2]);
            }
        }
    }

    int r0 = n0 + w * 16 + g;
    if (wsel == 0) {
        // theta: pre-scale by log2(e) so attention can use exp2
#pragma unroll
        for (int nt = 0; nt < 16; nt++) {
            int c = nt * 8 + t * 2;
            float v0 = O[nt][0] * LOG2E, v1 = O[nt][1] * LOG2E;
            float v2 = O[nt][2] * LOG2E, v3 = O[nt][3] * LOG2E;
            __nv_bfloat16 h0 = bhi(v0), h1 = bhi(v1), h2 = bhi(v2), h3 = bhi(v3);
            __nv_bfloat162 H0; H0.x = h0; H0.y = h1;
            __nv_bfloat162 L0; L0.x = blo(v0, h0); L0.y = blo(v1, h1);
            __nv_bfloat162 H1; H1.x = h2; H1.y = h3;
            __nv_bfloat162 L1; L1.x = blo(v2, h2); L1.y = blo(v3, h3);
            *(__nv_bfloat162*)(g_th + (size_t)r0 * DD + c)       = H0;
            *(__nv_bfloat162*)(g_tl + (size_t)r0 * DD + c)       = L0;
            *(__nv_bfloat162*)(g_th + (size_t)(r0 + 8) * DD + c) = H1;
            *(__nv_bfloat162*)(g_tl + (size_t)(r0 + 8) * DD + c) = L1;
        }
    } else {
        float* out = (wsel == 1) ? g_phi : g_gv;
#pragma unroll
        for (int nt = 0; nt < 16; nt++) {
            int c = nt * 8 + t * 2;
            float2 a = {O[nt][0], O[nt][1]};
            float2 b = {O[nt][2], O[nt][3]};
            *(float2*)(out + (size_t)r0 * DD + c)       = a;
            *(float2*)(out + (size_t)(r0 + 8) * DD + c) = b;
        }
    }
}

// ---------------- kernel 2: pool -> K,V hi/lo ----------------
__global__ void pool_kernel()
{
    int i = blockIdx.x * blockDim.x + threadIdx.x;
    if (i >= BSZ * NN * DD) return;
    int m = (i / DD) % NN;
    float kv = 0.f, vv = 0.f;
    if (m < MM) {
        kv = fmaxf(g_phi[i], g_phi[i + DD]);
        vv = fmaxf(g_gv[i],  g_gv[i + DD]);
    }
    __nv_bfloat16 kh = bhi(kv), vh = bhi(vv);
    g_kh[i] = kh; g_kl[i] = blo(kv, kh);
    g_vh[i] = vh; g_vl[i] = blo(vv, vh);
}

// ---------------- kernel 3: flash attention ----------------
// 128 q/CTA, 256 thr. Q fragments in registers. 64-key tiles, 3-stage cp.async.
#define RSTR   272
#define SS     69632          // stage stride
#define SKH    0
#define SKL    17408
#define SVH    34816
#define SVL    52224
#define ATT_SMEM (3 * SS)     // 208896

__global__ void __launch_bounds__(256, 1) attn_kernel()
{
    extern __shared__ __align__(16) char sm[];
    const uint32_t sb = s2u(sm);
    const int tid = threadIdx.x, w = tid >> 5, lane = tid & 31;
    const int b = blockIdx.y, q0 = blockIdx.x * 128;
    const int g = lane >> 2, t = lane & 3;

    const uint4* kh4 = (const uint4*)(g_kh + (size_t)b * NN * DD);
    const uint4* kl4 = (const uint4*)(g_kl + (size_t)b * NN * DD);
    const uint4* vh4 = (const uint4*)(g_vh + (size_t)b * NN * DD);
    const uint4* vl4 = (const uint4*)(g_vl + (size_t)b * NN * DD);

    // ---- stage Q in smem (stage0 area), ldsm to registers, then free it ----
    {
        const uint4* qh = (const uint4*)(g_th + ((size_t)b * NN + q0) * DD);
        const uint4* ql = (const uint4*)(g_tl + ((size_t)b * NN + q0) * DD);
#pragma unroll
        for (int i = 0; i < 8; i++) {
            int f = tid + i * 256;
            uint32_t off = (uint32_t)(f >> 4) * RSTR + (uint32_t)(f & 15) * 16;
            *(uint4*)(sm + off) = qh[f];
            *(uint4*)(sm + 34816 + off) = ql[f];
        }
    }
    __syncthreads();
    uint32_t Qh[8][4], Ql[8][4];
    {
        const uint32_t qa = sb + (uint32_t)(w * 16 + (lane & 15)) * RSTR
                          + (uint32_t)(lane >> 4) * 16;
#pragma unroll
        for (int kc = 0; kc < 8; kc++) {
            ldsm_x4(Qh[kc], qa + kc * 32);
            ldsm_x4(Ql[kc], qa + 34816 + kc * 32);
        }
    }
    __syncthreads();    // Q fragments safely in regs; stage0 reusable

    // per-thread cp.async offsets: 1024 uint4 per buffer, 4 chunks of 256
    uint32_t soff[4]; uint32_t goff[4];
#pragma unroll
    for (int i = 0; i < 4; i++) {
        int f = tid + i * 256;
        soff[i] = (uint32_t)(f >> 4) * RSTR + (uint32_t)(f & 15) * 16;
        goff[i] = (uint32_t)f;
    }

    // prologue: tiles 0,1,2 into stages 0,1,2 (one commit group per tile)
#pragma unroll
    for (int pt = 0; pt < 3; pt++) {
        uint32_t base = sb + (uint32_t)pt * SS;
        uint32_t gi = (uint32_t)pt * 1024;
#pragma unroll
        for (int i = 0; i < 4; i++) {
            cpa16(base + SKH + soff[i], kh4 + gi + goff[i]);
            cpa16(base + SKL + soff[i], kl4 + gi + goff[i]);
            cpa16(base + SVH + soff[i], vh4 + gi + goff[i]);
            cpa16(base + SVL + soff[i], vl4 + gi + goff[i]);
        }
        CPA_COMMIT();
    }

    float O[16][4];
#pragma unroll
    for (int i = 0; i < 16; i++)
#pragma unroll
        for (int j = 0; j < 4; j++) O[i][j] = 0.f;
    float mA = -1e30f, mB = -1e30f, lA = 0.f, lB = 0.f;

    const uint32_t kfrag = (uint32_t)(lane & 7) * RSTR + (uint32_t)((lane >> 3) & 1) * 16
                         + (uint32_t)(lane >> 4) * (8 * RSTR);
    const uint32_t vfrag = (uint32_t)(lane & 15) * RSTR + (uint32_t)(lane >> 4) * 16;

    int stage = 0;
    for (int kt = 0; kt < NKT; kt++) {
        // tile kt ready when ≤(pending-1) groups outstanding
        if (kt <= NKT - 3)
            asm volatile("cp.async.wait_group 2;" ::: "memory");
        else if (kt == NKT - 2)
            asm volatile("cp.async.wait_group 1;" ::: "memory");
        else
            asm volatile("cp.async.wait_group 0;" ::: "memory");
        __syncthreads();

        const uint32_t kb = sb + (uint32_t)stage * SS + SKH + kfrag;
        const uint32_t vb = sb + (uint32_t)stage * SS + SVH + vfrag;

        // ---- S = Q K^T (bf16x3), K via ldsm.x4 pairs ----
        float S[8][4];
#pragma unroll
        for (int i = 0; i < 8; i++)
#pragma unroll
            for (int j = 0; j < 4; j++) S[i][j] = 0.f;

#pragma unroll
        for (int kc = 0; kc < 8; kc++) {
#pragma unroll
            for (int np = 0; np < 4; np++) {
                uint32_t Bh[4], Bl[4];
                uint32_t ka = kb + (uint32_t)np * (16 * RSTR) + kc * 32;
                ldsm_x4(Bh, ka);
                ldsm_x4(Bl, ka + (SKL - SKH));
                mma16816(S[2 * np],     Qh[kc], &Bh[0]);
                mma16816(S[2 * np],     Ql[kc], &Bh[0]);
                mma16816(S[2 * np],     Qh[kc], &Bl[0]);
                mma16816(S[2 * np + 1], Qh[kc], &Bh[2]);
                mma16816(S[2 * np + 1], Ql[kc], &Bh[2]);
                mma16816(S[2 * np + 1], Qh[kc], &Bl[2]);
            }
        }

        // mask key m=4095 (last col of last tile)
        if (kt == NKT - 1 && t == 3) { S[7][1] = -1e30f; S[7][3] = -1e30f; }

        // ---- online softmax (base-2; theta pre-scaled by log2 e) ----
        float mlA = -1e30f, mlB = -1e30f;
#pragma unroll
        for (int nt = 0; nt < 8; nt++) {
            mlA = fmaxf(mlA, fmaxf(S[nt][0], S[nt][1]));
            mlB = fmaxf(mlB, fmaxf(S[nt][2], S[nt][3]));
        }
        mlA = fmaxf(mlA, __shfl_xor_sync(0xffffffffu, mlA, 1));
        mlA = fmaxf(mlA, __shfl_xor_sync(0xffffffffu, mlA, 2));
        mlB = fmaxf(mlB, __shfl_xor_sync(0xffffffffu, mlB, 1));
        mlB = fmaxf(mlB, __shfl_xor_sync(0xffffffffu, mlB, 2));

        // conditional rescale (skipped once max stabilizes)
        if (mlA > mA) {
            float mn = mlA;
            float sc = exp2f(mA - mn);
            mA = mn; lA *= sc;
#pragma unroll
            for (int i = 0; i < 16; i++) { O[i][0] *= sc; O[i][1] *= sc; }
        }
        if (mlB > mB) {
            float mn = mlB;
            float sc = exp2f(mB - mn);
            mB = mn; lB *= sc;
#pragma unroll
            for (int i = 0; i < 16; i++) { O[i][2] *= sc; O[i][3] *= sc; }
        }

        float lsA = 0.f, lsB = 0.f;
#pragma unroll
        for (int nt = 0; nt < 8; nt++) {
            S[nt][0] = exp2f(S[nt][0] - mA);
            S[nt][1] = exp2f(S[nt][1] - mA);
            S[nt][2] = exp2f(S[nt][2] - mB);
            S[nt][3] = exp2f(S[nt][3] - mB);
            lsA += S[nt][0] + S[nt][1];
            lsB += S[nt][2] + S[nt][3];
        }
        lsA += __shfl_xor_sync(0xffffffffu, lsA, 1);
        lsA += __shfl_xor_sync(0xffffffffu, lsA, 2);
        lsB += __shfl_xor_sync(0xffffffffu, lsB, 1);
        lsB += __shfl_xor_sync(0xffffffffu, lsB, 2);
        lA += lsA;
        lB += lsB;

        // ---- O += P V (bf16x3) ----
#pragma unroll
        for (int kk = 0; kk < 4; kk++) {
            uint32_t Ph[4], Pl[4];
            {
                const float* s0 = S[2 * kk];
                const float* s1 = S[2 * kk + 1];
                float lo[8];
#pragma unroll
                for (int e = 0; e < 4; e++) {
                    float p0 = s0[e], p1 = s1[e];
                    float h0 = __uint_as_float(__float_as_uint(p0) & 0xffff0000u);
                    float h1 = __uint_as_float(__float_as_uint(p1) & 0xffff0000u);
                    lo[e] = p0 - h0; lo[4 + e] = p1 - h1;
                }
                Ph[0] = __byte_perm(__float_as_uint(s0[0]), __float_as_uint(s0[1]), 0x7632);
                Ph[1] = __byte_perm(__float_as_uint(s0[2]), __float_as_uint(s0[3]), 0x7632);
                Ph[2] = __byte_perm(__float_as_uint(s1[0]), __float_as_uint(s1[1]), 0x7632);
                Ph[3] = __byte_perm(__float_as_uint(s1[2]), __float_as_uint(s1[3]), 0x7632);
                Pl[0] = packbf(lo[0], lo[1]); Pl[1] = packbf(lo[2], lo[3]);
                Pl[2] = packbf(lo[4], lo[5]); Pl[3] = packbf(lo[6], lo[7]);
            }
#pragma unroll
            for (int nd = 0; nd < 8; nd++) {
                uint32_t Vh[4], Vl[4];
                uint32_t va = vb + (uint32_t)kk * 16 * RSTR + (uint32_t)nd * 32;
                ldsm_x4t(Vh, va);
                ldsm_x4t(Vl, va + (SVL - SVH));
                mma16816(O[2 * nd],     Ph, &Vh[0]);
                mma16816(O[2 * nd],     Pl, &Vh[0]);
                mma16816(O[2 * nd],     Ph, &Vl[0]);
                mma16816(O[2 * nd + 1], Ph, &Vh[2]);
                mma16816(O[2 * nd + 1], Pl, &Vh[2]);
                mma16816(O[2 * nd + 1], Ph, &Vl[2]);
            }
        }
        __syncthreads();      // all warps done reading this stage

        // refill this stage with tile kt+3
        if (kt + 3 < NKT) {
            uint32_t base = sb + (uint32_t)stage * SS;
            uint32_t gi = (uint32_t)(kt + 3) * 1024;
#pragma unroll
            for (int i = 0; i < 4; i++) {
                cpa16(base + SKH + soff[i], kh4 + gi + goff[i]);
                cpa16(base + SKL + soff[i], kl4 + gi + goff[i]);
                cpa16(base + SVH + soff[i], vh4 + gi + goff[i]);
                cpa16(base + SVL + soff[i], vl4 + gi + goff[i]);
            }
            CPA_COMMIT();
        }
        stage = (stage + 1 == 3) ? 0 : stage + 1;
    }

    // epilogue
    float invA = 1.f / lA, invB = 1.f / lB;
    float* yA = g_y + ((size_t)b * NN + q0 + w * 16 + g) * DD;
    float* yB = yA + 8 * DD;
#pragma unroll
    for (int nd = 0; nd < 16; nd++) {
        int c = nd * 8 + t * 2;
        float2 oa = {O[nd][0] * invA, O[nd][1] * invA};
        float2 ob = {O[nd][2] * invB, O[nd][3] * invB};
        *(float2*)(yA + c) = oa;
        *(float2*)(yB + c) = ob;
    }
}

// ---------------- kernel 4: z = x + y @ Wf ----------------
#define OY_STR 132
#define OW_STR 68
#define OUT_SMEM (128 * OY_STR * 4 + 128 * OW_STR * 4)

__global__ void __launch_bounds__(256, 2) out_kernel(const float* __restrict__ x,
                                                     const float* __restrict__ Wf,
                                                     float* __restrict__ z)
{
    extern __shared__ __align__(16) float osm[];
    float* Ys  = osm;
    float* Wfs = osm + 128 * OY_STR;

    const int tid = threadIdx.x, ty = tid >> 4, tx = tid & 15;
    const int row0 = blockIdx.x * 128, c0 = blockIdx.y * 64;

    {
        const float4* src = (const float4*)(g_y + (size_t)row0 * DD);
#pragma unroll
        for (int p = 0; p < 16; p++) {
            int f = tid + p * 256, r = f >> 5, c = (f & 31) * 4;
            *(float4*)&Ys[r * OY_STR + c] = src[f];
        }
    }
    {
#pragma unroll
        for (int p = 0; p < 8; p++) {
            int f = tid + p * 256, r = f >> 4, c = (f & 15) * 4;
            *(float4*)&Wfs[r * OW_STR + c] = *(const float4*)&Wf[(size_t)r * CC + c0 + c];
        }
    }
    __syncthreads();

    float acc[8][4];
#pragma unroll
    for (int i = 0; i < 8; i++)
#pragma unroll
        for (int j = 0; j < 4; j++) acc[i][j] = 0.f;

#pragma unroll 4
    for (int k = 0; k < DD; k++) {
        float4 wv = *(float4*)&Wfs[k * OW_STR + tx * 4];
        float a[8];
#pragma unroll
        for (int i = 0; i < 8; i++) a[i] = Ys[(ty * 8 + i) * OY_STR + k];
#pragma unroll
        for (int i = 0; i < 8; i++) {
            acc[i][0] = fmaf(a[i], wv.x, acc[i][0]);
            acc[i][1] = fmaf(a[i], wv.y, acc[i][1]);
            acc[i][2] = fmaf(a[i], wv.z, acc[i][2]);
            acc[i][3] = fmaf(a[i], wv.w, acc[i][3]);
        }
    }

#pragma unroll
    for (int i = 0; i < 8; i++) {
        size_t base = (size_t)(row0 + ty * 8 + i) * CC + c0 + tx * 4;
        float4 xv = *(const float4*)&x[base];
        float4 o = {xv.x + acc[i][0], xv.y + acc[i][1], xv.z + acc[i][2], xv.w + acc[i][3]};
        *(float4*)&z[base] = o;
    }
}

// ---------------- launch ----------------
extern "C" void kernel_launch(void* const* d_in, const int* in_sizes, int n_in,
                              void* d_out, int out_size)
{
    const float* x  = (const float*)d_in[0];
    const float* Wt = (const float*)d_in[1];
    const float* Wp = (const float*)d_in[2];
    const float* Wg = (const float*)d_in[3];
    const float* Wf = (const float*)d_in[4];
    float* z = (float*)d_out;

    cudaFuncSetAttribute(proj_kernel, cudaFuncAttributeMaxDynamicSharedMemorySize, PROJ_SMEM);
    cudaFuncSetAttribute(attn_kernel, cudaFuncAttributeMaxDynamicSharedMemorySize, ATT_SMEM);
    cudaFuncSetAttribute(out_kernel,  cudaFuncAttributeMaxDynamicSharedMemorySize, OUT_SMEM);

    conv_kernel<<<(BSZ * NN * CC / 4 + 255) / 256, 256>>>(x, Wt, Wp, Wg);
    proj_kernel<<<dim3(BSZ * NN / 128, 3), 256, PROJ_SMEM>>>();
    pool_kernel<<<(BSZ * NN * DD) / 256, 256>>>();
    attn_kernel<<<dim3(NN / 128, BSZ), 256, ATT_SMEM>>>();
    out_kernel<<<dim3(BSZ * NN / 128, CC / 64), 256, OUT_SMEM>>>(x, Wf, z);
}

// round 13
// speedup vs baseline: 1.1843x; 1.0629x over previous
#include <cuda_runtime.h>
#include <cuda_bf16.h>
#include <cstdint>

#define BSZ 4
#define CC  256
#define DD  128
#define NN  4096
#define MM  4095
#define NKT 64              // key tiles of 64

// ---------------- scratch ----------------
__device__ __align__(16) __nv_bfloat16 g_th[BSZ*NN*DD];
__device__ __align__(16) __nv_bfloat16 g_tl[BSZ*NN*DD];
__device__ __align__(16) float g_phi[BSZ*NN*DD];
__device__ __align__(16) float g_gv [BSZ*NN*DD];
__device__ __align__(16) __nv_bfloat16 g_kh[BSZ*NN*DD];
__device__ __align__(16) __nv_bfloat16 g_kl[BSZ*NN*DD];
__device__ __align__(16) __nv_bfloat16 g_vh[BSZ*NN*DD];
__device__ __align__(16) __nv_bfloat16 g_vl[BSZ*NN*DD];
__device__ __align__(16) __nv_bfloat16 g_yh[BSZ*NN*DD];
__device__ __align__(16) __nv_bfloat16 g_yl[BSZ*NN*DD];

// ---------------- helpers ----------------
__device__ __forceinline__ uint32_t s2u(const void* p){
    uint32_t a;
    asm("{ .reg .u64 t; cvta.to.shared.u64 t, %1; cvt.u32.u64 %0, t; }" : "=r"(a) : "l"(p));
    return a;
}
__device__ __forceinline__ void ldsm_x4(uint32_t* r, uint32_t a){
    asm volatile("ldmatrix.sync.aligned.m8n8.x4.shared.b16 {%0,%1,%2,%3}, [%4];"
        : "=r"(r[0]),"=r"(r[1]),"=r"(r[2]),"=r"(r[3]) : "r"(a));
}
__device__ __forceinline__ void ldsm_x4t(uint32_t* r, uint32_t a){
    asm volatile("ldmatrix.sync.aligned.m8n8.x4.trans.shared.b16 {%0,%1,%2,%3}, [%4];"
        : "=r"(r[0]),"=r"(r[1]),"=r"(r[2]),"=r"(r[3]) : "r"(a));
}
__device__ __forceinline__ void mma16816(float* c, const uint32_t* a, const uint32_t* b){
    asm volatile("mma.sync.aligned.m16n8k16.row.col.f32.bf16.bf16.f32 "
        "{%0,%1,%2,%3}, {%4,%5,%6,%7}, {%8,%9}, {%0,%1,%2,%3};"
        : "+f"(c[0]),"+f"(c[1]),"+f"(c[2]),"+f"(c[3])
        : "r"(a[0]),"r"(a[1]),"r"(a[2]),"r"(a[3]),"r"(b[0]),"r"(b[1]));
}
__device__ __forceinline__ uint32_t packbf(float lo, float hi){
    uint32_t r; asm("cvt.rn.bf16x2.f32 %0, %1, %2;" : "=r"(r) : "f"(hi), "f"(lo)); return r;
}
__device__ __forceinline__ void cpa16(uint32_t s, const void* g){
    asm volatile("cp.async.cg.shared.global [%0], [%1], 16;" :: "r"(s), "l"(g));
}
#define CPA_COMMIT() asm volatile("cp.async.commit_group;" ::: "memory")
__device__ __forceinline__ __nv_bfloat16 bhi(float v){ return __float2bfloat16(v); }
__device__ __forceinline__ __nv_bfloat16 blo(float v, __nv_bfloat16 h){
    return __float2bfloat16(v - __bfloat162float(h));
}
// split a float4 into hi/lo bf16x2 pairs and store (8 bytes each) to smem
__device__ __forceinline__ void split_store(char* smH, char* smL, float4 v){
    __nv_bfloat16 h0 = bhi(v.x), h1 = bhi(v.y), h2 = bhi(v.z), h3 = bhi(v.w);
    __nv_bfloat162 H0; H0.x = h0; H0.y = h1;
    __nv_bfloat162 H1; H1.x = h2; H1.y = h3;
    __nv_bfloat162 L0; L0.x = blo(v.x, h0); L0.y = blo(v.y, h1);
    __nv_bfloat162 L1; L1.x = blo(v.z, h2); L1.y = blo(v.w, h3);
    *(__nv_bfloat162*)(smH)     = H0;
    *(__nv_bfloat162*)(smH + 4) = H1;
    *(__nv_bfloat162*)(smL)     = L0;
    *(__nv_bfloat162*)(smL + 4) = L1;
}

// ---------------- kernel 1: projections via mma.sync bf16x3 (fp32 in, split inline) --
#define PX_STR 144
#define PW_STR 272
#define P_XH 0
#define P_XL 18432
#define P_WH 36864
#define P_WL 54272
#define PROJ_SMEM 71680
#define LOG2E 1.4426950408889634f

__global__ void __launch_bounds__(256, 2) proj_kernel(const float* __restrict__ x,
                                                      const float* __restrict__ Wt,
                                                      const float* __restrict__ Wp,
                                                      const float* __restrict__ Wg)
{
    extern __shared__ __align__(16) char sm[];
    const uint32_t sb = s2u(sm);
    const int tid = threadIdx.x, w = tid >> 5, lane = tid & 31;
    const int n0 = blockIdx.x * 128, wsel = blockIdx.y;
    const int g = lane >> 2, t = lane & 3;

    const float4* x4 = (const float4*)x;
    const float4* W4 = (const float4*)((wsel == 0) ? Wt : (wsel == 1) ? Wp : Wg);

    float O[16][4];
#pragma unroll
    for (int i = 0; i < 16; i++)
#pragma unroll
        for (int j = 0; j < 4; j++) O[i][j] = 0.f;

    const uint32_t xaddr0 = sb + P_XH + (uint32_t)(w * 16 + (lane & 15)) * PX_STR
                          + (uint32_t)(lane >> 4) * 16;
    const uint32_t waddr0 = sb + P_WH + (uint32_t)(lane & 15) * PW_STR
                          + (uint32_t)(lane >> 4) * 16;

    for (int ch = 0; ch < 4; ch++) {
        __syncthreads();
        // X tile 128 rows x 64 cols fp32 -> hi/lo bf16: 2048 float4, 8/thread
#pragma unroll
        for (int i = 0; i < 8; i++) {
            int f = tid + i * 256, r = f >> 4, c4 = f & 15;
            float4 v = x4[(size_t)(n0 + r) * (CC / 4) + ch * 16 + c4];
            uint32_t off = (uint32_t)r * PX_STR + (uint32_t)c4 * 8;
            split_store(sm + P_XH + off, sm + P_XL + off, v);
        }
        // W tile 64 rows x 128 cols fp32 -> hi/lo: 2048 float4, 8/thread
#pragma unroll
        for (int i = 0; i < 8; i++) {
            int f = tid + i * 256, r = f >> 5, c4 = f & 31;
            float4 v = W4[(size_t)(ch * 64 + r) * (DD / 4) + c4];
            uint32_t off = (uint32_t)r * PW_STR + (uint32_t)c4 * 8;
            split_store(sm + P_WH + off, sm + P_WL + off, v);
        }
        __syncthreads();

#pragma unroll
        for (int kc = 0; kc < 4; kc++) {
            uint32_t Ah[4], Al[4];
            uint32_t xa = xaddr0 + kc * 32;
            ldsm_x4(Ah, xa);
            ldsm_x4(Al, xa + (P_XL - P_XH));
#pragma unroll
            for (int nd = 0; nd < 8; nd++) {
                uint32_t Bh[4], Bl[4];
                uint32_t wa = waddr0 + (uint32_t)kc * 16 * PW_STR + (uint32_t)nd * 32;
                ldsm_x4t(Bh, wa);
                ldsm_x4t(Bl, wa + (P_WL - P_WH));
                mma16816(O[2 * nd],     Ah, &Bh[0]);
                mma16816(O[2 * nd],     Al, &Bh[0]);
                mma16816(O[2 * nd],     Ah, &Bl[0]);
                mma16816(O[2 * nd + 1], Ah, &Bh[2]);
                mma16816(O[2 * nd + 1], Al, &Bh[2]);
                mma16816(O[2 * nd + 1], Ah, &Bl[2]);
            }
        }
    }

    int r0 = n0 + w * 16 + g;
    if (wsel == 0) {
        // theta: pre-scale by log2(e) so attention can use exp2
#pragma unroll
        for (int nt = 0; nt < 16; nt++) {
            int c = nt * 8 + t * 2;
            float v0 = O[nt][0] * LOG2E, v1 = O[nt][1] * LOG2E;
            float v2 = O[nt][2] * LOG2E, v3 = O[nt][3] * LOG2E;
            __nv_bfloat16 h0 = bhi(v0), h1 = bhi(v1), h2 = bhi(v2), h3 = bhi(v3);
            __nv_bfloat162 H0; H0.x = h0; H0.y = h1;
            __nv_bfloat162 L0; L0.x = blo(v0, h0); L0.y = blo(v1, h1);
            __nv_bfloat162 H1; H1.x = h2; H1.y = h3;
            __nv_bfloat162 L1; L1.x = blo(v2, h2); L1.y = blo(v3, h3);
            *(__nv_bfloat162*)(g_th + (size_t)r0 * DD + c)       = H0;
            *(__nv_bfloat162*)(g_tl + (size_t)r0 * DD + c)       = L0;
            *(__nv_bfloat162*)(g_th + (size_t)(r0 + 8) * DD + c) = H1;
            *(__nv_bfloat162*)(g_tl + (size_t)(r0 + 8) * DD + c) = L1;
        }
    } else {
        float* out = (wsel == 1) ? g_phi : g_gv;
#pragma unroll
        for (int nt = 0; nt < 16; nt++) {
            int c = nt * 8 + t * 2;
            float2 a = {O[nt][0], O[nt][1]};
            float2 b = {O[nt][2], O[nt][3]};
            *(float2*)(out + (size_t)r0 * DD + c)       = a;
            *(float2*)(out + (size_t)(r0 + 8) * DD + c) = b;
        }
    }
}

// ---------------- kernel 2: pool -> K,V hi/lo ----------------
__global__ void pool_kernel()
{
    int i = blockIdx.x * blockDim.x + threadIdx.x;
    if (i >= BSZ * NN * DD) return;
    int m = (i / DD) % NN;
    float kv = 0.f, vv = 0.f;
    if (m < MM) {
        kv = fmaxf(g_phi[i], g_phi[i + DD]);
        vv = fmaxf(g_gv[i],  g_gv[i + DD]);
    }
    __nv_bfloat16 kh = bhi(kv), vh = bhi(vv);
    g_kh[i] = kh; g_kl[i] = blo(kv, kh);
    g_vh[i] = vh; g_vl[i] = blo(vv, vh);
}

// ---------------- kernel 3: flash attention (frozen from R11/R12) ----------------
#define RSTR   272
#define SS     69632
#define SKH    0
#define SKL    17408
#define SVH    34816
#define SVL    52224
#define ATT_SMEM (3 * SS)

__global__ void __launch_bounds__(256, 1) attn_kernel()
{
    extern __shared__ __align__(16) char sm[];
    const uint32_t sb = s2u(sm);
    const int tid = threadIdx.x, w = tid >> 5, lane = tid & 31;
    const int b = blockIdx.y, q0 = blockIdx.x * 128;
    const int g = lane >> 2, t = lane & 3;

    const uint4* kh4 = (const uint4*)(g_kh + (size_t)b * NN * DD);
    const uint4* kl4 = (const uint4*)(g_kl + (size_t)b * NN * DD);
    const uint4* vh4 = (const uint4*)(g_vh + (size_t)b * NN * DD);
    const uint4* vl4 = (const uint4*)(g_vl + (size_t)b * NN * DD);

    // stage Q in smem, ldsm to registers, then free
    {
        const uint4* qh = (const uint4*)(g_th + ((size_t)b * NN + q0) * DD);
        const uint4* ql = (const uint4*)(g_tl + ((size_t)b * NN + q0) * DD);
#pragma unroll
        for (int i = 0; i < 8; i++) {
            int f = tid + i * 256;
            uint32_t off = (uint32_t)(f >> 4) * RSTR + (uint32_t)(f & 15) * 16;
            *(uint4*)(sm + off) = qh[f];
            *(uint4*)(sm + 34816 + off) = ql[f];
        }
    }
    __syncthreads();
    uint32_t Qh[8][4], Ql[8][4];
    {
        const uint32_t qa = sb + (uint32_t)(w * 16 + (lane & 15)) * RSTR
                          + (uint32_t)(lane >> 4) * 16;
#pragma unroll
        for (int kc = 0; kc < 8; kc++) {
            ldsm_x4(Qh[kc], qa + kc * 32);
            ldsm_x4(Ql[kc], qa + 34816 + kc * 32);
        }
    }
    __syncthreads();

    uint32_t soff[4]; uint32_t goff[4];
#pragma unroll
    for (int i = 0; i < 4; i++) {
        int f = tid + i * 256;
        soff[i] = (uint32_t)(f >> 4) * RSTR + (uint32_t)(f & 15) * 16;
        goff[i] = (uint32_t)f;
    }

#pragma unroll
    for (int pt = 0; pt < 3; pt++) {
        uint32_t base = sb + (uint32_t)pt * SS;
        uint32_t gi = (uint32_t)pt * 1024;
#pragma unroll
        for (int i = 0; i < 4; i++) {
            cpa16(base + SKH + soff[i], kh4 + gi + goff[i]);
            cpa16(base + SKL + soff[i], kl4 + gi + goff[i]);
            cpa16(base + SVH + soff[i], vh4 + gi + goff[i]);
            cpa16(base + SVL + soff[i], vl4 + gi + goff[i]);
        }
        CPA_COMMIT();
    }

    float O[16][4];
#pragma unroll
    for (int i = 0; i < 16; i++)
#pragma unroll
        for (int j = 0; j < 4; j++) O[i][j] = 0.f;
    float mA = -1e30f, mB = -1e30f, lA = 0.f, lB = 0.f;

    const uint32_t kfrag = (uint32_t)(lane & 7) * RSTR + (uint32_t)((lane >> 3) & 1) * 16
                         + (uint32_t)(lane >> 4) * (8 * RSTR);
    const uint32_t vfrag = (uint32_t)(lane & 15) * RSTR + (uint32_t)(lane >> 4) * 16;

    int stage = 0;
    for (int kt = 0; kt < NKT; kt++) {
        if (kt <= NKT - 3)
            asm volatile("cp.async.wait_group 2;" ::: "memory");
        else if (kt == NKT - 2)
            asm volatile("cp.async.wait_group 1;" ::: "memory");
        else
            asm volatile("cp.async.wait_group 0;" ::: "memory");
        __syncthreads();

        const uint32_t kb = sb + (uint32_t)stage * SS + SKH + kfrag;
        const uint32_t vb = sb + (uint32_t)stage * SS + SVH + vfrag;

        float S[8][4];
#pragma unroll
        for (int i = 0; i < 8; i++)
#pragma unroll
            for (int j = 0; j < 4; j++) S[i][j] = 0.f;

#pragma unroll
        for (int kc = 0; kc < 8; kc++) {
#pragma unroll
            for (int np = 0; np < 4; np++) {
                uint32_t Bh[4], Bl[4];
                uint32_t ka = kb + (uint32_t)np * (16 * RSTR) + kc * 32;
                ldsm_x4(Bh, ka);
                ldsm_x4(Bl, ka + (SKL - SKH));
                mma16816(S[2 * np],     Qh[kc], &Bh[0]);
                mma16816(S[2 * np],     Ql[kc], &Bh[0]);
                mma16816(S[2 * np],     Qh[kc], &Bl[0]);
                mma16816(S[2 * np + 1], Qh[kc], &Bh[2]);
                mma16816(S[2 * np + 1], Ql[kc], &Bh[2]);
                mma16816(S[2 * np + 1], Qh[kc], &Bl[2]);
            }
        }

        if (kt == NKT - 1 && t == 3) { S[7][1] = -1e30f; S[7][3] = -1e30f; }

        float mlA = -1e30f, mlB = -1e30f;
#pragma unroll
        for (int nt = 0; nt < 8; nt++) {
            mlA = fmaxf(mlA, fmaxf(S[nt][0], S[nt][1]));
            mlB = fmaxf(mlB, fmaxf(S[nt][2], S[nt][3]));
        }
        mlA = fmaxf(mlA, __shfl_xor_sync(0xffffffffu, mlA, 1));
        mlA = fmaxf(mlA, __shfl_xor_sync(0xffffffffu, mlA, 2));
        mlB = fmaxf(mlB, __shfl_xor_sync(0xffffffffu, mlB, 1));
        mlB = fmaxf(mlB, __shfl_xor_sync(0xffffffffu, mlB, 2));

        if (mlA > mA) {
            float mn = mlA;
            float sc = exp2f(mA - mn);
            mA = mn; lA *= sc;
#pragma unroll
            for (int i = 0; i < 16; i++) { O[i][0] *= sc; O[i][1] *= sc; }
        }
        if (mlB > mB) {
            float mn = mlB;
            float sc = exp2f(mB - mn);
            mB = mn; lB *= sc;
#pragma unroll
            for (int i = 0; i < 16; i++) { O[i][2] *= sc; O[i][3] *= sc; }
        }

        float lsA = 0.f, lsB = 0.f;
#pragma unroll
        for (int nt = 0; nt < 8; nt++) {
            S[nt][0] = exp2f(S[nt][0] - mA);
            S[nt][1] = exp2f(S[nt][1] - mA);
            S[nt][2] = exp2f(S[nt][2] - mB);
            S[nt][3] = exp2f(S[nt][3] - mB);
            lsA += S[nt][0] + S[nt][1];
            lsB += S[nt][2] + S[nt][3];
        }
        lsA += __shfl_xor_sync(0xffffffffu, lsA, 1);
        lsA += __shfl_xor_sync(0xffffffffu, lsA, 2);
        lsB += __shfl_xor_sync(0xffffffffu, lsB, 1);
        lsB += __shfl_xor_sync(0xffffffffu, lsB, 2);
        lA += lsA;
        lB += lsB;

#pragma unroll
        for (int kk = 0; kk < 4; kk++) {
            uint32_t Ph[4], Pl[4];
            {
                const float* s0 = S[2 * kk];
                const float* s1 = S[2 * kk + 1];
                float lo[8];
#pragma unroll
                for (int e = 0; e < 4; e++) {
                    float p0 = s0[e], p1 = s1[e];
                    float h0 = __uint_as_float(__float_as_uint(p0) & 0xffff0000u);
                    float h1 = __uint_as_float(__float_as_uint(p1) & 0xffff0000u);
                    lo[e] = p0 - h0; lo[4 + e] = p1 - h1;
                }
                Ph[0] = __byte_perm(__float_as_uint(s0[0]), __float_as_uint(s0[1]), 0x7632);
                Ph[1] = __byte_perm(__float_as_uint(s0[2]), __float_as_uint(s0[3]), 0x7632);
                Ph[2] = __byte_perm(__float_as_uint(s1[0]), __float_as_uint(s1[1]), 0x7632);
                Ph[3] = __byte_perm(__float_as_uint(s1[2]), __float_as_uint(s1[3]), 0x7632);
                Pl[0] = packbf(lo[0], lo[1]); Pl[1] = packbf(lo[2], lo[3]);
                Pl[2] = packbf(lo[4], lo[5]); Pl[3] = packbf(lo[6], lo[7]);
            }
#pragma unroll
            for (int nd = 0; nd < 8; nd++) {
                uint32_t Vh[4], Vl[4];
                uint32_t va = vb + (uint32_t)kk * 16 * RSTR + (uint32_t)nd * 32;
                ldsm_x4t(Vh, va);
                ldsm_x4t(Vl, va + (SVL - SVH));
                mma16816(O[2 * nd],     Ph, &Vh[0]);
                mma16816(O[2 * nd],     Pl, &Vh[0]);
                mma16816(O[2 * nd],     Ph, &Vl[0]);
                mma16816(O[2 * nd + 1], Ph, &Vh[2]);
                mma16816(O[2 * nd + 1], Pl, &Vh[2]);
                mma16816(O[2 * nd + 1], Ph, &Vl[2]);
            }
        }
        __syncthreads();

        if (kt + 3 < NKT) {
            uint32_t base = sb + (uint32_t)stage * SS;
            uint32_t gi = (uint32_t)(kt + 3) * 1024;
#pragma unroll
            for (int i = 0; i < 4; i++) {
                cpa16(base + SKH + soff[i], kh4 + gi + goff[i]);
                cpa16(base + SKL + soff[i], kl4 + gi + goff[i]);
                cpa16(base + SVH + soff[i], vh4 + gi + goff[i]);
                cpa16(base + SVL + soff[i], vl4 + gi + goff[i]);
            }
            CPA_COMMIT();
        }
        stage = (stage + 1 == 3) ? 0 : stage + 1;
    }

    // epilogue: write y as bf16 hi/lo (feeds out_kernel's mma directly)
    float invA = 1.f / lA, invB = 1.f / lB;
    size_t rowA = (size_t)b * NN + q0 + w * 16 + g;
    size_t rowB = rowA + 8;
#pragma unroll
    for (int nd = 0; nd < 16; nd++) {
        int c = nd * 8 + t * 2;
        float a0 = O[nd][0] * invA, a1 = O[nd][1] * invA;
        float b0 = O[nd][2] * invB, b1 = O[nd][3] * invB;
        __nv_bfloat16 ha0 = bhi(a0), ha1 = bhi(a1), hb0 = bhi(b0), hb1 = bhi(b1);
        __nv_bfloat162 HA; HA.x = ha0; HA.y = ha1;
        __nv_bfloat162 LA; LA.x = blo(a0, ha0); LA.y = blo(a1, ha1);
        __nv_bfloat162 HB; HB.x = hb0; HB.y = hb1;
        __nv_bfloat162 LB; LB.x = blo(b0, hb0); LB.y = blo(b1, hb1);
        *(__nv_bfloat162*)(g_yh + rowA * DD + c) = HA;
        *(__nv_bfloat162*)(g_yl + rowA * DD + c) = LA;
        *(__nv_bfloat162*)(g_yh + rowB * DD + c) = HB;
        *(__nv_bfloat162*)(g_yl + rowB * DD + c) = LB;
    }
}

// ---------------- kernel 4: z = x + y @ Wf via mma.sync bf16x3 ----------------
// CTA 128 rows x 128 cols, K = 128 in 2 chunks of 64; same smem plan as proj.
__global__ void __launch_bounds__(256, 2) out_kernel(const float* __restrict__ x,
                                                     const float* __restrict__ Wf,
                                                     float* __restrict__ z)
{
    extern __shared__ __align__(16) char sm[];
    const uint32_t sb = s2u(sm);
    const int tid = threadIdx.x, w = tid >> 5, lane = tid & 31;
    const int row0 = blockIdx.x * 128, c0 = blockIdx.y * 128;
    const int g = lane >> 2, t = lane & 3;

    const uint4* yh4 = (const uint4*)g_yh;
    const uint4* yl4 = (const uint4*)g_yl;
    const float4* Wf4 = (const float4*)Wf;

    float O[16][4];
#pragma unroll
    for (int i = 0; i < 16; i++)
#pragma unroll
        for (int j = 0; j < 4; j++) O[i][j] = 0.f;

    const uint32_t xaddr0 = sb + P_XH + (uint32_t)(w * 16 + (lane & 15)) * PX_STR
                          + (uint32_t)(lane >> 4) * 16;
    const uint32_t waddr0 = sb + P_WH + (uint32_t)(lane & 15) * PW_STR
                          + (uint32_t)(lane >> 4) * 16;

    for (int ch = 0; ch < 2; ch++) {
        __syncthreads();
        // Y tile 128 rows x 64 bf16 hi/lo: 1024 uint4 each, 4/thread
#pragma unroll
        for (int i = 0; i < 4; i++) {
            int f = tid + i * 256, r = f >> 3, c = f & 7;
            uint32_t off = (uint32_t)r * PX_STR + (uint32_t)c * 16;
            size_t src = (size_t)(row0 + r) * (DD / 8) + ch * 8 + c;
            *(uint4*)(sm + P_XH + off) = yh4[src];
            *(uint4*)(sm + P_XL + off) = yl4[src];
        }
        // Wf tile 64 rows x 128 cols fp32 -> hi/lo: 2048 float4, 8/thread
#pragma unroll
        for (int i = 0; i < 8; i++) {
            int f = tid + i * 256, r = f >> 5, c4 = f & 31;
            float4 v = Wf4[(size_t)(ch * 64 + r) * (CC / 4) + (c0 >> 2) + c4];
            uint32_t off = (uint32_t)r * PW_STR + (uint32_t)c4 * 8;
            split_store(sm + P_WH + off, sm + P_WL + off, v);
        }
        __syncthreads();

#pragma unroll
        for (int kc = 0; kc < 4; kc++) {
            uint32_t Ah[4], Al[4];
            uint32_t xa = xaddr0 + kc * 32;
            ldsm_x4(Ah, xa);
            ldsm_x4(Al, xa + (P_XL - P_XH));
#pragma unroll
            for (int nd = 0; nd < 8; nd++) {
                uint32_t Bh[4], Bl[4];
                uint32_t wa = waddr0 + (uint32_t)kc * 16 * PW_STR + (uint32_t)nd * 32;
                ldsm_x4t(Bh, wa);
                ldsm_x4t(Bl, wa + (P_WL - P_WH));
                mma16816(O[2 * nd],     Ah, &Bh[0]);
                mma16816(O[2 * nd],     Al, &Bh[0]);
                mma16816(O[2 * nd],     Ah, &Bl[0]);
                mma16816(O[2 * nd + 1], Ah, &Bh[2]);
                mma16816(O[2 * nd + 1], Al, &Bh[2]);
                mma16816(O[2 * nd + 1], Ah, &Bl[2]);
            }
        }
    }

    // epilogue: residual add + store
    int r0 = row0 + w * 16 + g;
#pragma unroll
    for (int nt = 0; nt < 16; nt++) {
        int c = c0 + nt * 8 + t * 2;
        size_t baseA = (size_t)r0 * CC + c;
        size_t baseB = (size_t)(r0 + 8) * CC + c;
        float2 xa = *(const float2*)&x[baseA];
        float2 xb = *(const float2*)&x[baseB];
        float2 oa = {xa.x + O[nt][0], xa.y + O[nt][1]};
        float2 ob = {xb.x + O[nt][2], xb.y + O[nt][3]};
        *(float2*)&z[baseA] = oa;
        *(float2*)&z[baseB] = ob;
    }
}

// ---------------- launch ----------------
extern "C" void kernel_launch(void* const* d_in, const int* in_sizes, int n_in,
                              void* d_out, int out_size)
{
    const float* x  = (const float*)d_in[0];
    const float* Wt = (const float*)d_in[1];
    const float* Wp = (const float*)d_in[2];
    const float* Wg = (const float*)d_in[3];
    const float* Wf = (const float*)d_in[4];
    float* z = (float*)d_out;

    cudaFuncSetAttribute(proj_kernel, cudaFuncAttributeMaxDynamicSharedMemorySize, PROJ_SMEM);
    cudaFuncSetAttribute(attn_kernel, cudaFuncAttributeMaxDynamicSharedMemorySize, ATT_SMEM);
    cudaFuncSetAttribute(out_kernel,  cudaFuncAttributeMaxDynamicSharedMemorySize, PROJ_SMEM);

    proj_kernel<<<dim3(BSZ * NN / 128, 3), 256, PROJ_SMEM>>>(x, Wt, Wp, Wg);
    pool_kernel<<<(BSZ * NN * DD) / 256, 256>>>();
    attn_kernel<<<dim3(NN / 128, BSZ), 256, ATT_SMEM>>>();
    out_kernel<<<dim3(BSZ * NN / 128, CC / 128), 256, PROJ_SMEM>>>(x, Wf, z);
}